// round 1
// baseline (speedup 1.0000x reference)
#include <cuda_runtime.h>

// ---------------------------------------------------------------------------
// Transformer block, fp32 SIMT baseline.
// B=2, T=2048, D=1024, H=16, HS=64, FF=4096
// Pipeline: LN1 -> QKV gemms -> flash attention (causal) -> add+LN2 ->
//           FFN1 (bias+relu) -> FFN2 (bias+residual) -> out
// ---------------------------------------------------------------------------

#define Bc   2
#define Tc   2048
#define Dc   1024
#define Hc   16
#define HSc  64
#define Fc   4096
#define EPSc 1e-5f
#define NROW (Bc*Tc)            // 4096 rows

// Scratch (device globals: allocation-free rule)
__device__ float g_x   [NROW*Dc];        // LN1 output
__device__ float g_q   [Bc*Hc*Tc*HSc];
__device__ float g_k   [Bc*Hc*Tc*HSc];
__device__ float g_v   [Bc*Hc*Tc*HSc];
__device__ float g_attn[NROW*Dc];        // attention out, [B,T,D]
__device__ float g_res [NROW*Dc];        // embds + attn
__device__ float g_y   [NROW*Dc];        // LN2 output
__device__ float g_ff1 [NROW*Fc];        // relu(y@W1+b1)

// ---------------------------------------------------------------------------
// LayerNorm over a 1024-wide row. 256 threads, 4 elems each.
// ---------------------------------------------------------------------------
__global__ void __launch_bounds__(256) ln1_kernel(const float* __restrict__ in,
                                                  const float* __restrict__ gg,
                                                  const float* __restrict__ bb)
{
    __shared__ float sbs[8], sbq[8];
    int row  = blockIdx.x;
    int base = threadIdx.x * 4;
    const float* x = in + (size_t)row * Dc;
    float4 v = *(const float4*)(x + base);
    float s = v.x + v.y + v.z + v.w;
    float q = v.x*v.x + v.y*v.y + v.z*v.z + v.w*v.w;
#pragma unroll
    for (int o = 16; o; o >>= 1) {
        s += __shfl_xor_sync(0xffffffffu, s, o);
        q += __shfl_xor_sync(0xffffffffu, q, o);
    }
    if ((threadIdx.x & 31) == 0) { sbs[threadIdx.x >> 5] = s; sbq[threadIdx.x >> 5] = q; }
    __syncthreads();
    s = 0.f; q = 0.f;
#pragma unroll
    for (int i = 0; i < 8; i++) { s += sbs[i]; q += sbq[i]; }
    float mean = s * (1.f / Dc);
    float var  = q * (1.f / Dc) - mean * mean;
    float inv  = rsqrtf(var + EPSc);
    float4 g4 = *(const float4*)(gg + base);
    float4 b4 = *(const float4*)(bb + base);
    float4 o;
    o.x = (v.x - mean) * inv * g4.x + b4.x;
    o.y = (v.y - mean) * inv * g4.y + b4.y;
    o.z = (v.z - mean) * inv * g4.z + b4.z;
    o.w = (v.w - mean) * inv * g4.w + b4.w;
    *(float4*)(g_x + (size_t)row * Dc + base) = o;
}

// resid = embds + attn ; y = LN(resid)
__global__ void __launch_bounds__(256) add_ln_kernel(const float* __restrict__ in,
                                                     const float* __restrict__ gg,
                                                     const float* __restrict__ bb)
{
    __shared__ float sbs[8], sbq[8];
    int row  = blockIdx.x;
    int base = threadIdx.x * 4;
    float4 e = *(const float4*)(in     + (size_t)row * Dc + base);
    float4 a = *(const float4*)(g_attn + (size_t)row * Dc + base);
    float4 v = make_float4(e.x + a.x, e.y + a.y, e.z + a.z, e.w + a.w);
    *(float4*)(g_res + (size_t)row * Dc + base) = v;
    float s = v.x + v.y + v.z + v.w;
    float q = v.x*v.x + v.y*v.y + v.z*v.z + v.w*v.w;
#pragma unroll
    for (int o = 16; o; o >>= 1) {
        s += __shfl_xor_sync(0xffffffffu, s, o);
        q += __shfl_xor_sync(0xffffffffu, q, o);
    }
    if ((threadIdx.x & 31) == 0) { sbs[threadIdx.x >> 5] = s; sbq[threadIdx.x >> 5] = q; }
    __syncthreads();
    s = 0.f; q = 0.f;
#pragma unroll
    for (int i = 0; i < 8; i++) { s += sbs[i]; q += sbq[i]; }
    float mean = s * (1.f / Dc);
    float var  = q * (1.f / Dc) - mean * mean;
    float inv  = rsqrtf(var + EPSc);
    float4 g4 = *(const float4*)(gg + base);
    float4 b4 = *(const float4*)(bb + base);
    float4 o;
    o.x = (v.x - mean) * inv * g4.x + b4.x;
    o.y = (v.y - mean) * inv * g4.y + b4.y;
    o.z = (v.z - mean) * inv * g4.z + b4.z;
    o.w = (v.w - mean) * inv * g4.w + b4.w;
    *(float4*)(g_y + (size_t)row * Dc + base) = o;
}

// ---------------------------------------------------------------------------
// 64x64 C tile, BK=16, 256 threads, 4x4 micro-tile per thread.
// A row-major [M,K] (lda), B row-major [K,N] (ldb) already offset to nBase.
// ---------------------------------------------------------------------------
__device__ __forceinline__ void gemm_tile(const float* __restrict__ A, int lda,
                                          const float* __restrict__ Bm, int ldb,
                                          int K, int mBase, float acc[4][4],
                                          float (*As)[64], float (*Bs)[64])
{
    int tid  = threadIdx.x;
    int tx   = tid & 15, ty = tid >> 4;
    int aRow = tid >> 2, aCol = (tid & 3) * 4;
    int bRow = tid >> 4, bCol = (tid & 15) * 4;
    for (int k0 = 0; k0 < K; k0 += 16) {
        float4 a4 = *(const float4*)(A + (size_t)(mBase + aRow) * lda + k0 + aCol);
        As[aCol + 0][aRow] = a4.x;
        As[aCol + 1][aRow] = a4.y;
        As[aCol + 2][aRow] = a4.z;
        As[aCol + 3][aRow] = a4.w;
        *(float4*)&Bs[bRow][bCol] = *(const float4*)(Bm + (size_t)(k0 + bRow) * ldb + bCol);
        __syncthreads();
#pragma unroll
        for (int kk = 0; kk < 16; kk++) {
            float4 av = *(const float4*)&As[kk][ty * 4];
            float4 bv = *(const float4*)&Bs[kk][tx * 4];
            float ar[4] = {av.x, av.y, av.z, av.w};
            float br[4] = {bv.x, bv.y, bv.z, bv.w};
#pragma unroll
            for (int i = 0; i < 4; i++)
#pragma unroll
                for (int j = 0; j < 4; j++)
                    acc[i][j] += ar[i] * br[j];
        }
        __syncthreads();
    }
}

// QKV: grid (64, 1, 48). z = sel*16 + h. C[m, e] -> q/k/v[b,h,t,e]
__global__ void __launch_bounds__(256) qkv_kernel(const float* __restrict__ Wq,
                                                  const float* __restrict__ Wk,
                                                  const float* __restrict__ Wv)
{
    __shared__ float As[16][64], Bs[16][64];
    int z   = blockIdx.z;
    int h   = z & 15, sel = z >> 4;
    const float* W  = (sel == 0) ? Wq : ((sel == 1) ? Wk : Wv);
    float*      dst = (sel == 0) ? g_q : ((sel == 1) ? g_k : g_v);
    const float* Bm = W + (size_t)h * Dc * HSc;
    int mBase = blockIdx.x * 64;
    float acc[4][4] = {};
    gemm_tile(g_x, Dc, Bm, HSc, Dc, mBase, acc, As, Bs);
    int tx = threadIdx.x & 15, ty = threadIdx.x >> 4;
#pragma unroll
    for (int i = 0; i < 4; i++) {
        int m = mBase + ty * 4 + i;
        int b = m >> 11, t = m & 2047;
        float* o = dst + (((size_t)(b * Hc + h)) * Tc + t) * HSc + tx * 4;
#pragma unroll
        for (int j = 0; j < 4; j++) o[j] = acc[i][j];
    }
}

// FFN1: grid (64, 64). relu(y @ W1 + b1)
__global__ void __launch_bounds__(256) ffn1_kernel(const float* __restrict__ W1,
                                                   const float* __restrict__ b1)
{
    __shared__ float As[16][64], Bs[16][64];
    int mBase = blockIdx.x * 64, nBase = blockIdx.y * 64;
    float acc[4][4] = {};
    gemm_tile(g_y, Dc, W1 + nBase, Fc, Dc, mBase, acc, As, Bs);
    int tx = threadIdx.x & 15, ty = threadIdx.x >> 4;
#pragma unroll
    for (int i = 0; i < 4; i++) {
        int m = mBase + ty * 4 + i;
#pragma unroll
        for (int j = 0; j < 4; j++) {
            int n = nBase + tx * 4 + j;
            g_ff1[(size_t)m * Fc + n] = fmaxf(acc[i][j] + b1[n], 0.f);
        }
    }
}

// FFN2: grid (64, 16). out = ff1 @ W2 + b2 + resid
__global__ void __launch_bounds__(256) ffn2_kernel(const float* __restrict__ W2,
                                                   const float* __restrict__ b2,
                                                   float* __restrict__ out)
{
    __shared__ float As[16][64], Bs[16][64];
    int mBase = blockIdx.x * 64, nBase = blockIdx.y * 64;
    float acc[4][4] = {};
    gemm_tile(g_ff1, Fc, W2 + nBase, Dc, Fc, mBase, acc, As, Bs);
    int tx = threadIdx.x & 15, ty = threadIdx.x >> 4;
#pragma unroll
    for (int i = 0; i < 4; i++) {
        int m = mBase + ty * 4 + i;
#pragma unroll
        for (int j = 0; j < 4; j++) {
            int n = nBase + tx * 4 + j;
            out[(size_t)m * Dc + n] = acc[i][j] + b2[n] + g_res[(size_t)m * Dc + n];
        }
    }
}

// ---------------------------------------------------------------------------
// Flash attention, causal. grid (T/64, B*H), 256 threads.
// Thread tid: query row ql = tid>>2, sub = tid&3 owns 16 key-cols (S phase)
// and 16 output dims (PV phase). Smem stride 68 = conflict-free float4.
// ---------------------------------------------------------------------------
#define SSTR 68
__global__ void __launch_bounds__(256) attn_kernel()
{
    extern __shared__ float sm[];
    float* Qs = sm;
    float* Ks = sm + 64 * SSTR;
    float* Vs = sm + 2 * 64 * SSTR;
    float* Ss = sm + 3 * 64 * SSTR;

    int qt = blockIdx.x, bh = blockIdx.y;
    const float* Q = g_q + (size_t)bh * Tc * HSc;
    const float* K = g_k + (size_t)bh * Tc * HSc;
    const float* V = g_v + (size_t)bh * Tc * HSc;

    int tid = threadIdx.x;
    int ql  = tid >> 2, sub = tid & 3;

#pragma unroll
    for (int i = 0; i < 4; i++) {
        int idx = tid + i * 256;
        int row = idx >> 4, col = (idx & 15) * 4;
        *(float4*)&Qs[row * SSTR + col] =
            *(const float4*)(Q + (size_t)(qt * 64 + row) * HSc + col);
    }

    float m_i = -1e30f, l_i = 0.f;
    float acc[16];
#pragma unroll
    for (int i = 0; i < 16; i++) acc[i] = 0.f;
    int q_glob = qt * 64 + ql;

    for (int kt = 0; kt <= qt; kt++) {
        __syncthreads();                 // previous PV done before overwrite
#pragma unroll
        for (int i = 0; i < 4; i++) {
            int idx = tid + i * 256;
            int row = idx >> 4, col = (idx & 15) * 4;
            *(float4*)&Ks[row * SSTR + col] =
                *(const float4*)(K + (size_t)(kt * 64 + row) * HSc + col);
            *(float4*)&Vs[row * SSTR + col] =
                *(const float4*)(V + (size_t)(kt * 64 + row) * HSc + col);
        }
        __syncthreads();

        // S = Q K^T for my 16 key columns
        float dotv[16];
#pragma unroll
        for (int j = 0; j < 16; j++) dotv[j] = 0.f;
        const float4* qrow = (const float4*)&Qs[ql * SSTR];
#pragma unroll
        for (int d4 = 0; d4 < 16; d4++) {
            float4 qv = qrow[d4];
#pragma unroll
            for (int j = 0; j < 16; j++) {
                float4 kv = *(const float4*)&Ks[(sub * 16 + j) * SSTR + d4 * 4];
                dotv[j] += qv.x * kv.x;
                dotv[j] += qv.y * kv.y;
                dotv[j] += qv.z * kv.z;
                dotv[j] += qv.w * kv.w;
            }
        }

        // scale (d^-0.5 = 1/32), causal mask, row max (shfl across 4 subs)
        float mx = -1e30f;
        bool diag = (kt == qt);
#pragma unroll
        for (int j = 0; j < 16; j++) {
            float d = dotv[j] * 0.03125f;
            if (diag && (kt * 64 + sub * 16 + j) > q_glob) d = -1e30f;
            dotv[j] = d;
            mx = fmaxf(mx, d);
        }
        mx = fmaxf(mx, __shfl_xor_sync(0xffffffffu, mx, 1));
        mx = fmaxf(mx, __shfl_xor_sync(0xffffffffu, mx, 2));
        float mnew  = fmaxf(m_i, mx);
        float scale = __expf(m_i - mnew);
        float lsum = 0.f;
#pragma unroll
        for (int j = 0; j < 16; j++) {
            float p = __expf(dotv[j] - mnew);
            lsum += p;
            Ss[ql * SSTR + sub * 16 + j] = p;
        }
        lsum += __shfl_xor_sync(0xffffffffu, lsum, 1);
        lsum += __shfl_xor_sync(0xffffffffu, lsum, 2);
        l_i = l_i * scale + lsum;
        m_i = mnew;
#pragma unroll
        for (int i = 0; i < 16; i++) acc[i] *= scale;
        __syncwarp();                    // Ss row visible to all 4 subs (same warp)

        // PV: accumulate my 16 output dims over all 64 keys
#pragma unroll 4
        for (int k = 0; k < 64; k++) {
            float p = Ss[ql * SSTR + k];
            const float4* vr = (const float4*)&Vs[k * SSTR + sub * 16];
            float4 v0 = vr[0], v1 = vr[1], v2 = vr[2], v3 = vr[3];
            acc[0]  += p * v0.x; acc[1]  += p * v0.y; acc[2]  += p * v0.z; acc[3]  += p * v0.w;
            acc[4]  += p * v1.x; acc[5]  += p * v1.y; acc[6]  += p * v1.z; acc[7]  += p * v1.w;
            acc[8]  += p * v2.x; acc[9]  += p * v2.y; acc[10] += p * v2.z; acc[11] += p * v2.w;
            acc[12] += p * v3.x; acc[13] += p * v3.y; acc[14] += p * v3.z; acc[15] += p * v3.w;
        }
    }

    float inv = 1.f / l_i;
    int b = bh >> 4, h = bh & 15;
    float* o = g_attn + ((size_t)b * Tc + q_glob) * Dc + h * HSc + sub * 16;
#pragma unroll
    for (int i = 0; i < 4; i++) {
        float4 w = make_float4(acc[i*4+0] * inv, acc[i*4+1] * inv,
                               acc[i*4+2] * inv, acc[i*4+3] * inv);
        *(float4*)&o[i * 4] = w;
    }
}

// ---------------------------------------------------------------------------
extern "C" void kernel_launch(void* const* d_in, const int* in_sizes, int n_in,
                              void* d_out, int out_size)
{
    (void)in_sizes; (void)n_in; (void)out_size;
    const float* embds = (const float*)d_in[0];
    const float* Wq    = (const float*)d_in[1];
    const float* Wk    = (const float*)d_in[2];
    const float* Wv    = (const float*)d_in[3];
    const float* ln1_g = (const float*)d_in[4];
    const float* ln1_b = (const float*)d_in[5];
    const float* ln2_g = (const float*)d_in[6];
    const float* ln2_b = (const float*)d_in[7];
    const float* W1    = (const float*)d_in[8];
    const float* b1    = (const float*)d_in[9];
    const float* W2    = (const float*)d_in[10];
    const float* b2    = (const float*)d_in[11];
    float* out = (float*)d_out;

    static const size_t attn_smem = 4 * 64 * SSTR * sizeof(float); // 69632 B
    cudaFuncSetAttribute(attn_kernel, cudaFuncAttributeMaxDynamicSharedMemorySize,
                         (int)attn_smem);

    ln1_kernel  <<<NROW, 256>>>(embds, ln1_g, ln1_b);
    qkv_kernel  <<<dim3(64, 1, 48), 256>>>(Wq, Wk, Wv);
    attn_kernel <<<dim3(Tc / 64, Bc * Hc), 256, attn_smem>>>();
    add_ln_kernel<<<NROW, 256>>>(embds, ln2_g, ln2_b);
    ffn1_kernel <<<dim3(64, 64), 256>>>(W1, b1);
    ffn2_kernel <<<dim3(64, 16), 256>>>(W2, b2, out);
}

// round 3
// speedup vs baseline: 1.3472x; 1.3472x over previous
#include <cuda_runtime.h>
#include <cuda_bf16.h>
#include <cstdint>

// ---------------------------------------------------------------------------
// Transformer block. B=2, T=2048, D=1024, H=16, HS=64, FF=4096
// GEMMs: mma.sync bf16 split hi/lo (3-MMA fp32 emulation), cp.async pipeline.
// Attention: SIMT flash (next target).
// ---------------------------------------------------------------------------

#define Bc   2
#define Tc   2048
#define Dc   1024
#define Hc   16
#define HSc  64
#define Fc   4096
#define EPSc 1e-5f
#define NROW (Bc*Tc)            // 4096 rows

// ---------------- scratch (device globals; allocation-free rule) -----------
__device__ __nv_bfloat16 g_xh [NROW*Dc];
__device__ __nv_bfloat16 g_xl [NROW*Dc];
__device__ __nv_bfloat16 g_yh [NROW*Dc];
__device__ __nv_bfloat16 g_yl [NROW*Dc];
__device__ __nv_bfloat16 g_wqkvh[3*Dc*Dc];   // [3072 n, 1024 k]
__device__ __nv_bfloat16 g_wqkvl[3*Dc*Dc];
__device__ __nv_bfloat16 g_w1h[Fc*Dc];       // W1^T [4096, 1024]
__device__ __nv_bfloat16 g_w1l[Fc*Dc];
__device__ __nv_bfloat16 g_w2h[Dc*Fc];       // W2^T [1024, 4096]
__device__ __nv_bfloat16 g_w2l[Dc*Fc];
__device__ __nv_bfloat16 g_ff1h[(size_t)NROW*Fc];
__device__ __nv_bfloat16 g_ff1l[(size_t)NROW*Fc];
__device__ float g_q   [Bc*Hc*Tc*HSc];
__device__ float g_k   [Bc*Hc*Tc*HSc];
__device__ float g_v   [Bc*Hc*Tc*HSc];
__device__ float g_attn[NROW*Dc];
__device__ float g_res [NROW*Dc];

// ---------------- PTX helpers ----------------------------------------------
__device__ __forceinline__ uint32_t smem_u32(const void* p) {
    uint32_t a;
    asm("{ .reg .u64 t; cvta.to.shared.u64 t, %1; cvt.u32.u64 %0, t; }"
        : "=r"(a) : "l"(p));
    return a;
}
__device__ __forceinline__ void cp16(uint32_t s, const void* g) {
    asm volatile("cp.async.cg.shared.global [%0], [%1], 16;" :: "r"(s), "l"(g));
}
#define CP_COMMIT() asm volatile("cp.async.commit_group;" ::: "memory")
#define CP_WAIT(n)  asm volatile("cp.async.wait_group %0;" :: "n"(n) : "memory")

__device__ __forceinline__ void ldm4(uint32_t* r, uint32_t addr) {
    asm volatile("ldmatrix.sync.aligned.m8n8.x4.shared.b16 {%0,%1,%2,%3}, [%4];"
        : "=r"(r[0]), "=r"(r[1]), "=r"(r[2]), "=r"(r[3]) : "r"(addr));
}
__device__ __forceinline__ void mma16816(float* d, const uint32_t* a, const uint32_t* b) {
    asm volatile("mma.sync.aligned.m16n8k16.row.col.f32.bf16.bf16.f32 "
        "{%0,%1,%2,%3}, {%4,%5,%6,%7}, {%8,%9}, {%0,%1,%2,%3};"
        : "+f"(d[0]), "+f"(d[1]), "+f"(d[2]), "+f"(d[3])
        : "r"(a[0]), "r"(a[1]), "r"(a[2]), "r"(a[3]), "r"(b[0]), "r"(b[1]));
}

__device__ __forceinline__ uint32_t pack_bf2(float a, float b) {
    __nv_bfloat162 h = __floats2bfloat162_rn(a, b);
    return *(uint32_t*)&h;
}
__device__ __forceinline__ void split1(float v, __nv_bfloat16& h, __nv_bfloat16& l) {
    h = __float2bfloat16_rn(v);
    l = __float2bfloat16_rn(v - __bfloat162float(h));
}

// ---------------------------------------------------------------------------
// LN kernels: write split bf16 hi/lo.
// ---------------------------------------------------------------------------
__device__ __forceinline__ void ln_body(float4 v, const float* gg, const float* bb,
                                        int base, __nv_bfloat16* dh, __nv_bfloat16* dl,
                                        size_t row)
{
    __shared__ float sbs[8], sbq[8];
    float s = v.x + v.y + v.z + v.w;
    float q = v.x*v.x + v.y*v.y + v.z*v.z + v.w*v.w;
#pragma unroll
    for (int o = 16; o; o >>= 1) {
        s += __shfl_xor_sync(0xffffffffu, s, o);
        q += __shfl_xor_sync(0xffffffffu, q, o);
    }
    if ((threadIdx.x & 31) == 0) { sbs[threadIdx.x >> 5] = s; sbq[threadIdx.x >> 5] = q; }
    __syncthreads();
    s = 0.f; q = 0.f;
#pragma unroll
    for (int i = 0; i < 8; i++) { s += sbs[i]; q += sbq[i]; }
    float mean = s * (1.f / Dc);
    float var  = q * (1.f / Dc) - mean * mean;
    float inv  = rsqrtf(var + EPSc);
    float4 g4 = *(const float4*)(gg + base);
    float4 b4 = *(const float4*)(bb + base);
    float o0 = (v.x - mean) * inv * g4.x + b4.x;
    float o1 = (v.y - mean) * inv * g4.y + b4.y;
    float o2 = (v.z - mean) * inv * g4.z + b4.z;
    float o3 = (v.w - mean) * inv * g4.w + b4.w;
    __nv_bfloat16 h0,h1,h2,h3,l0,l1,l2,l3;
    split1(o0,h0,l0); split1(o1,h1,l1); split1(o2,h2,l2); split1(o3,h3,l3);
    uint2 hp, lp;
    hp.x = pack_bf2(__bfloat162float(h0), __bfloat162float(h1));
    hp.y = pack_bf2(__bfloat162float(h2), __bfloat162float(h3));
    lp.x = pack_bf2(__bfloat162float(l0), __bfloat162float(l1));
    lp.y = pack_bf2(__bfloat162float(l2), __bfloat162float(l3));
    *(uint2*)(dh + row * Dc + base) = hp;
    *(uint2*)(dl + row * Dc + base) = lp;
}

__global__ void __launch_bounds__(256) ln1_kernel(const float* __restrict__ in,
                                                  const float* __restrict__ gg,
                                                  const float* __restrict__ bb)
{
    size_t row = blockIdx.x;
    int base = threadIdx.x * 4;
    float4 v = *(const float4*)(in + row * Dc + base);
    ln_body(v, gg, bb, base, g_xh, g_xl, row);
}

__global__ void __launch_bounds__(256) add_ln_kernel(const float* __restrict__ in,
                                                     const float* __restrict__ gg,
                                                     const float* __restrict__ bb)
{
    size_t row = blockIdx.x;
    int base = threadIdx.x * 4;
    float4 e = *(const float4*)(in     + row * Dc + base);
    float4 a = *(const float4*)(g_attn + row * Dc + base);
    float4 v = make_float4(e.x + a.x, e.y + a.y, e.z + a.z, e.w + a.w);
    *(float4*)(g_res + row * Dc + base) = v;
    ln_body(v, gg, bb, base, g_yh, g_yl, row);
}

// ---------------------------------------------------------------------------
// Weight transpose + split: dst[n*R + k] = split(src[k*C + n])
// ---------------------------------------------------------------------------
__global__ void __launch_bounds__(256) tsplit_kernel(const float* __restrict__ src,
                                                     __nv_bfloat16* __restrict__ dh,
                                                     __nv_bfloat16* __restrict__ dl,
                                                     int R, int C)
{
    __shared__ float t[32][33];
    int n0 = blockIdx.x * 32, k0 = blockIdx.y * 32;
    int tx = threadIdx.x, ty = threadIdx.y;
    for (int i = ty; i < 32; i += 8) t[i][tx] = src[(size_t)(k0 + i) * C + n0 + tx];
    __syncthreads();
    for (int i = ty; i < 32; i += 8) {
        float v = t[tx][i];
        __nv_bfloat16 h, l; split1(v, h, l);
        size_t o = (size_t)(n0 + i) * R + k0 + tx;
        dh[o] = h; dl[o] = l;
    }
}

__global__ void __launch_bounds__(256) qkv_tsplit_kernel(const float* __restrict__ Wq,
                                                         const float* __restrict__ Wk,
                                                         const float* __restrict__ Wv)
{
    __shared__ float t[32][33];
    int z = blockIdx.z;                    // 0..47
    int sel = z >> 4, h = z & 15;
    const float* src = (sel == 0 ? Wq : (sel == 1 ? Wk : Wv)) + (size_t)h * Dc * HSc;
    int n0 = blockIdx.x * 32, k0 = blockIdx.y * 32;
    int tx = threadIdx.x, ty = threadIdx.y;
    for (int i = ty; i < 32; i += 8) t[i][tx] = src[(size_t)(k0 + i) * HSc + n0 + tx];
    __syncthreads();
    for (int i = ty; i < 32; i += 8) {
        float v = t[tx][i];
        __nv_bfloat16 hh, ll; split1(v, hh, ll);
        size_t o = (size_t)(z * 64 + n0 + i) * Dc + k0 + tx;
        g_wqkvh[o] = hh; g_wqkvl[o] = ll;
    }
}

// ---------------------------------------------------------------------------
// Split-bf16 HMMA GEMM: C[128x128] = A[128xK] * B[128xK]^T, fp32 accum.
// 256 threads, 8 warps each 64x32 (4x4 of m16n8k16). BK=32, cp.async 2-stage.
// smem stage: Ah, Al, Bh, Bl each 128 rows x 64B (stride 80B) = 10240 B.
// Epilogue stages fp32 through smem [128][132] then fused global write.
// mode 0: QKV scatter; 1: relu(acc+b1)->split bf16; 2: acc+b2+res->out.
// ---------------------------------------------------------------------------
#define STRIDEB 80
#define MATB    (128*STRIDEB)       // 10240
#define STGB    (4*MATB)            // 40960
#define GSM_TOTAL (2*STGB)          // 81920 (>= 128*132*4 = 67584)

__global__ void __launch_bounds__(256) gemm_mma_kernel(
    const __nv_bfloat16* __restrict__ Ah, const __nv_bfloat16* __restrict__ Al,
    const __nv_bfloat16* __restrict__ Bh, const __nv_bfloat16* __restrict__ Bl,
    int K, int mode, const float* __restrict__ bias, float* __restrict__ outF)
{
    extern __shared__ char smc[];
    uint32_t sb = smem_u32(smc);
    int tid = threadIdx.x, lane = tid & 31, w = tid >> 5;
    int m0 = (w & 1) * 64, n0w = (w >> 1) * 32;
    int mBase = blockIdx.x * 128, nBase = blockIdx.y * 128;
    int nc = K >> 5;

    float acc[4][4][4];
#pragma unroll
    for (int i = 0; i < 4; i++)
#pragma unroll
        for (int j = 0; j < 4; j++)
#pragma unroll
            for (int r = 0; r < 4; r++) acc[i][j][r] = 0.f;

    auto load_chunk = [&](int c, int buf) {
        int kcol = c << 5;
        uint32_t stg = sb + buf * STGB;
#pragma unroll
        for (int i = tid; i < 512; i += 256) {
            int r = i >> 2, sg = i & 3;
            uint32_t so = stg + r * STRIDEB + sg * 16;
            size_t ga = (size_t)(mBase + r) * K + kcol + sg * 8;
            size_t gb = (size_t)(nBase + r) * K + kcol + sg * 8;
            cp16(so,            Ah + ga);
            cp16(so + MATB,     Al + ga);
            cp16(so + 2*MATB,   Bh + gb);
            cp16(so + 3*MATB,   Bl + gb);
        }
        CP_COMMIT();
    };

    load_chunk(0, 0);

    for (int c = 0; c < nc; ++c) {
        if (c + 1 < nc) load_chunk(c + 1, (c + 1) & 1);
        if (c + 1 < nc) CP_WAIT(1); else CP_WAIT(0);
        __syncthreads();

        uint32_t stg = sb + (c & 1) * STGB;
#pragma unroll
        for (int ks = 0; ks < 2; ks++) {
            uint32_t colb = ks * 32 + (lane >> 4) * 16;
            uint32_t ah[4][4], al[4][4], bh[4][2], bl[4][2];
#pragma unroll
            for (int mi = 0; mi < 4; mi++) {
                uint32_t ro = (uint32_t)(m0 + mi * 16 + (lane & 15)) * STRIDEB + colb;
                ldm4(ah[mi], stg + ro);
                ldm4(al[mi], stg + MATB + ro);
            }
#pragma unroll
            for (int p = 0; p < 2; p++) {
                uint32_t ro = (uint32_t)(n0w + p * 16 + (lane & 15)) * STRIDEB + colb;
                uint32_t q[4];
                ldm4(q, stg + 2*MATB + ro);
                bh[2*p][0] = q[0]; bh[2*p][1] = q[2];
                bh[2*p+1][0] = q[1]; bh[2*p+1][1] = q[3];
                ldm4(q, stg + 3*MATB + ro);
                bl[2*p][0] = q[0]; bl[2*p][1] = q[2];
                bl[2*p+1][0] = q[1]; bl[2*p+1][1] = q[3];
            }
#pragma unroll
            for (int mi = 0; mi < 4; mi++)
#pragma unroll
                for (int nj = 0; nj < 4; nj++) {
                    mma16816(acc[mi][nj], ah[mi], bh[nj]);
                    mma16816(acc[mi][nj], ah[mi], bl[nj]);
                    mma16816(acc[mi][nj], al[mi], bh[nj]);
                }
        }
        __syncthreads();
    }

    // ---- epilogue: regs -> smem fp32 [128][132] -> fused global write ----
    float* Es = (float*)smc;
#pragma unroll
    for (int mi = 0; mi < 4; mi++)
#pragma unroll
        for (int nj = 0; nj < 4; nj++) {
            int r0 = m0 + mi * 16 + (lane >> 2);
            int c0 = n0w + nj * 8 + (lane & 3) * 2;
            Es[r0 * 132 + c0]           = acc[mi][nj][0];
            Es[r0 * 132 + c0 + 1]       = acc[mi][nj][1];
            Es[(r0 + 8) * 132 + c0]     = acc[mi][nj][2];
            Es[(r0 + 8) * 132 + c0 + 1] = acc[mi][nj][3];
        }
    __syncthreads();

    if (mode == 0) {            // QKV scatter, f32
        for (int idx = tid; idx < 1024; idx += 256) {
            int r = idx >> 3, seg = idx & 7;
            int m = mBase + r, bb2 = m >> 11, t = m & 2047;
            int nn = nBase + seg * 16;
            int sel = nn >> 10, rem = nn & 1023, h = rem >> 6, e = rem & 63;
            float* dst = (sel == 0 ? g_q : (sel == 1 ? g_k : g_v)) +
                         (((size_t)(bb2 * Hc + h)) * Tc + t) * HSc + e;
            const float* es = &Es[r * 132 + seg * 16];
#pragma unroll
            for (int j = 0; j < 4; j++)
                *(float4*)(dst + j * 4) =
                    make_float4(es[j*4], es[j*4+1], es[j*4+2], es[j*4+3]);
        }
    } else if (mode == 1) {     // FFN1: relu(acc+b1) -> split bf16
        for (int idx = tid; idx < 1024; idx += 256) {
            int r = idx >> 3, seg = idx & 7;
            int m = mBase + r;
            int nn = nBase + seg * 16;
            const float* es = &Es[r * 132 + seg * 16];
            uint32_t hp[8], lp[8];
#pragma unroll
            for (int jj = 0; jj < 8; jj++) {
                float a   = fmaxf(es[2*jj]   + bias[nn + 2*jj],     0.f);
                float b2v = fmaxf(es[2*jj+1] + bias[nn + 2*jj + 1], 0.f);
                __nv_bfloat16 ha, la, hb, lb2;
                split1(a, ha, la); split1(b2v, hb, lb2);
                __nv_bfloat162 hh; hh.x = ha; hh.y = hb;
                __nv_bfloat162 llv; llv.x = la; llv.y = lb2;
                hp[jj] = *(uint32_t*)&hh; lp[jj] = *(uint32_t*)&llv;
            }
            size_t o = (size_t)m * Fc + nn;
            *(uint4*)(g_ff1h + o)     = make_uint4(hp[0], hp[1], hp[2], hp[3]);
            *(uint4*)(g_ff1h + o + 8) = make_uint4(hp[4], hp[5], hp[6], hp[7]);
            *(uint4*)(g_ff1l + o)     = make_uint4(lp[0], lp[1], lp[2], lp[3]);
            *(uint4*)(g_ff1l + o + 8) = make_uint4(lp[4], lp[5], lp[6], lp[7]);
        }
    } else {                    // FFN2: acc + b2 + res -> out
        for (int idx = tid; idx < 1024; idx += 256) {
            int r = idx >> 3, seg = idx & 7;
            int m = mBase + r;
            int nn = nBase + seg * 16;
            const float* es = &Es[r * 132 + seg * 16];
            float* dst = outF + (size_t)m * Dc + nn;
            const float* res = g_res + (size_t)m * Dc + nn;
#pragma unroll
            for (int j = 0; j < 4; j++) {
                float4 rv = *(const float4*)(res + j * 4);
                float4 ov;
                ov.x = es[j*4]   + bias[nn + j*4]     + rv.x;
                ov.y = es[j*4+1] + bias[nn + j*4 + 1] + rv.y;
                ov.z = es[j*4+2] + bias[nn + j*4 + 2] + rv.z;
                ov.w = es[j*4+3] + bias[nn + j*4 + 3] + rv.w;
                *(float4*)(dst + j * 4) = ov;
            }
        }
    }
}

// ---------------------------------------------------------------------------
// Flash attention, causal (SIMT). grid (T/64, B*H), 256 threads.
// ---------------------------------------------------------------------------
#define SSTR 68
__global__ void __launch_bounds__(256) attn_kernel()
{
    extern __shared__ float sm[];
    float* Qs = sm;
    float* Ks = sm + 64 * SSTR;
    float* Vs = sm + 2 * 64 * SSTR;
    float* Ss = sm + 3 * 64 * SSTR;

    int qt = blockIdx.x, bh = blockIdx.y;
    const float* Q = g_q + (size_t)bh * Tc * HSc;
    const float* K = g_k + (size_t)bh * Tc * HSc;
    const float* V = g_v + (size_t)bh * Tc * HSc;

    int tid = threadIdx.x;
    int ql  = tid >> 2, sub = tid & 3;

#pragma unroll
    for (int i = 0; i < 4; i++) {
        int idx = tid + i * 256;
        int row = idx >> 4, col = (idx & 15) * 4;
        *(float4*)&Qs[row * SSTR + col] =
            *(const float4*)(Q + (size_t)(qt * 64 + row) * HSc + col);
    }

    float m_i = -1e30f, l_i = 0.f;
    float acc[16];
#pragma unroll
    for (int i = 0; i < 16; i++) acc[i] = 0.f;
    int q_glob = qt * 64 + ql;

    for (int kt = 0; kt <= qt; kt++) {
        __syncthreads();
#pragma unroll
        for (int i = 0; i < 4; i++) {
            int idx = tid + i * 256;
            int row = idx >> 4, col = (idx & 15) * 4;
            *(float4*)&Ks[row * SSTR + col] =
                *(const float4*)(K + (size_t)(kt * 64 + row) * HSc + col);
            *(float4*)&Vs[row * SSTR + col] =
                *(const float4*)(V + (size_t)(kt * 64 + row) * HSc + col);
        }
        __syncthreads();

        float dotv[16];
#pragma unroll
        for (int j = 0; j < 16; j++) dotv[j] = 0.f;
        const float4* qrow = (const float4*)&Qs[ql * SSTR];
#pragma unroll
        for (int d4 = 0; d4 < 16; d4++) {
            float4 qv = qrow[d4];
#pragma unroll
            for (int j = 0; j < 16; j++) {
                float4 kv = *(const float4*)&Ks[(sub * 16 + j) * SSTR + d4 * 4];
                dotv[j] += qv.x * kv.x;
                dotv[j] += qv.y * kv.y;
                dotv[j] += qv.z * kv.z;
                dotv[j] += qv.w * kv.w;
            }
        }

        float mx = -1e30f;
        bool diag = (kt == qt);
#pragma unroll
        for (int j = 0; j < 16; j++) {
            float d = dotv[j] * 0.03125f;
            if (diag && (kt * 64 + sub * 16 + j) > q_glob) d = -1e30f;
            dotv[j] = d;
            mx = fmaxf(mx, d);
        }
        mx = fmaxf(mx, __shfl_xor_sync(0xffffffffu, mx, 1));
        mx = fmaxf(mx, __shfl_xor_sync(0xffffffffu, mx, 2));
        float mnew  = fmaxf(m_i, mx);
        float scale = __expf(m_i - mnew);
        float lsum = 0.f;
#pragma unroll
        for (int j = 0; j < 16; j++) {
            float p = __expf(dotv[j] - mnew);
            lsum += p;
            Ss[ql * SSTR + sub * 16 + j] = p;
        }
        lsum += __shfl_xor_sync(0xffffffffu, lsum, 1);
        lsum += __shfl_xor_sync(0xffffffffu, lsum, 2);
        l_i = l_i * scale + lsum;
        m_i = mnew;
#pragma unroll
        for (int i = 0; i < 16; i++) acc[i] *= scale;
        __syncwarp();

#pragma unroll 4
        for (int k = 0; k < 64; k++) {
            float p = Ss[ql * SSTR + k];
            const float4* vr = (const float4*)&Vs[k * SSTR + sub * 16];
            float4 v0 = vr[0], v1 = vr[1], v2 = vr[2], v3 = vr[3];
            acc[0]  += p * v0.x; acc[1]  += p * v0.y; acc[2]  += p * v0.z; acc[3]  += p * v0.w;
            acc[4]  += p * v1.x; acc[5]  += p * v1.y; acc[6]  += p * v1.z; acc[7]  += p * v1.w;
            acc[8]  += p * v2.x; acc[9]  += p * v2.y; acc[10] += p * v2.z; acc[11] += p * v2.w;
            acc[12] += p * v3.x; acc[13] += p * v3.y; acc[14] += p * v3.z; acc[15] += p * v3.w;
        }
    }

    float inv = 1.f / l_i;
    int b = bh >> 4, h = bh & 15;
    float* o = g_attn + ((size_t)b * Tc + q_glob) * Dc + h * HSc + sub * 16;
#pragma unroll
    for (int i = 0; i < 4; i++) {
        *(float4*)&o[i * 4] = make_float4(acc[i*4+0] * inv, acc[i*4+1] * inv,
                                          acc[i*4+2] * inv, acc[i*4+3] * inv);
    }
}

// ---------------------------------------------------------------------------
extern "C" void kernel_launch(void* const* d_in, const int* in_sizes, int n_in,
                              void* d_out, int out_size)
{
    (void)in_sizes; (void)n_in; (void)out_size;
    const float* embds = (const float*)d_in[0];
    const float* Wq    = (const float*)d_in[1];
    const float* Wk    = (const float*)d_in[2];
    const float* Wv    = (const float*)d_in[3];
    const float* ln1_g = (const float*)d_in[4];
    const float* ln1_b = (const float*)d_in[5];
    const float* ln2_g = (const float*)d_in[6];
    const float* ln2_b = (const float*)d_in[7];
    const float* W1    = (const float*)d_in[8];
    const float* b1    = (const float*)d_in[9];
    const float* W2    = (const float*)d_in[10];
    const float* b2    = (const float*)d_in[11];
    float* out = (float*)d_out;

    static const size_t attn_smem = 4 * 64 * SSTR * sizeof(float);
    cudaFuncSetAttribute(attn_kernel, cudaFuncAttributeMaxDynamicSharedMemorySize,
                         (int)attn_smem);
    cudaFuncSetAttribute(gemm_mma_kernel, cudaFuncAttributeMaxDynamicSharedMemorySize,
                         GSM_TOTAL);

    __nv_bfloat16 *xh, *xl, *yh, *yl, *wqh, *wql, *w1h, *w1l, *w2h, *w2l, *f1h, *f1l;
    cudaGetSymbolAddress((void**)&xh, g_xh);   cudaGetSymbolAddress((void**)&xl, g_xl);
    cudaGetSymbolAddress((void**)&yh, g_yh);   cudaGetSymbolAddress((void**)&yl, g_yl);
    cudaGetSymbolAddress((void**)&wqh, g_wqkvh); cudaGetSymbolAddress((void**)&wql, g_wqkvl);
    cudaGetSymbolAddress((void**)&w1h, g_w1h); cudaGetSymbolAddress((void**)&w1l, g_w1l);
    cudaGetSymbolAddress((void**)&w2h, g_w2h); cudaGetSymbolAddress((void**)&w2l, g_w2l);
    cudaGetSymbolAddress((void**)&f1h, g_ff1h); cudaGetSymbolAddress((void**)&f1l, g_ff1l);

    ln1_kernel<<<NROW, 256>>>(embds, ln1_g, ln1_b);
    qkv_tsplit_kernel<<<dim3(2, 32, 48), dim3(32, 8)>>>(Wq, Wk, Wv);
    tsplit_kernel<<<dim3(128, 32), dim3(32, 8)>>>(W1, w1h, w1l, Dc, Fc);
    tsplit_kernel<<<dim3(32, 128), dim3(32, 8)>>>(W2, w2h, w2l, Fc, Dc);

    // QKV: A = x split [4096,1024], B = wqkv [3072,1024]
    gemm_mma_kernel<<<dim3(32, 24), 256, GSM_TOTAL>>>(xh, xl, wqh, wql,
                                                      Dc, 0, nullptr, nullptr);
    attn_kernel<<<dim3(Tc / 64, Bc * Hc), 256, attn_smem>>>();
    add_ln_kernel<<<NROW, 256>>>(embds, ln2_g, ln2_b);
    // FFN1: A = y [4096,1024], B = w1t [4096,1024]
    gemm_mma_kernel<<<dim3(32, 32), 256, GSM_TOTAL>>>(yh, yl, w1h, w1l,
                                                      Dc, 1, b1, nullptr);
    // FFN2: A = ff1 [4096,4096], B = w2t [1024,4096]
    gemm_mma_kernel<<<dim3(32, 8), 256, GSM_TOTAL>>>(f1h, f1l, w2h, w2l,
                                                     Fc, 2, b2, out);
}

// round 4
// speedup vs baseline: 4.9371x; 3.6646x over previous
#include <cuda_runtime.h>
#include <cuda_bf16.h>
#include <cstdint>

// ---------------------------------------------------------------------------
// Transformer block. B=2, T=2048, D=1024, H=16, HS=64, FF=4096
// GEMMs + flash attention all on mma.sync bf16 split hi/lo (fp32 emulation).
// ---------------------------------------------------------------------------

#define Bc   2
#define Tc   2048
#define Dc   1024
#define Hc   16
#define HSc  64
#define Fc   4096
#define EPSc 1e-5f
#define NROW (Bc*Tc)            // 4096 rows

// ---------------- scratch (device globals; allocation-free rule) -----------
__device__ __nv_bfloat16 g_xh [NROW*Dc];
__device__ __nv_bfloat16 g_xl [NROW*Dc];
__device__ __nv_bfloat16 g_yh [NROW*Dc];
__device__ __nv_bfloat16 g_yl [NROW*Dc];
__device__ __nv_bfloat16 g_wqkvh[3*Dc*Dc];   // [3072 n, 1024 k]
__device__ __nv_bfloat16 g_wqkvl[3*Dc*Dc];
__device__ __nv_bfloat16 g_w1h[Fc*Dc];       // W1^T [4096, 1024]
__device__ __nv_bfloat16 g_w1l[Fc*Dc];
__device__ __nv_bfloat16 g_w2h[Dc*Fc];       // W2^T [1024, 4096]
__device__ __nv_bfloat16 g_w2l[Dc*Fc];
__device__ __nv_bfloat16 g_ff1h[(size_t)NROW*Fc];
__device__ __nv_bfloat16 g_ff1l[(size_t)NROW*Fc];
// q/k/v split bf16, layout [bh][t][64]
__device__ __nv_bfloat16 g_qh[Bc*Hc*Tc*HSc];
__device__ __nv_bfloat16 g_ql[Bc*Hc*Tc*HSc];
__device__ __nv_bfloat16 g_kh[Bc*Hc*Tc*HSc];
__device__ __nv_bfloat16 g_kl[Bc*Hc*Tc*HSc];
__device__ __nv_bfloat16 g_vh[Bc*Hc*Tc*HSc];
__device__ __nv_bfloat16 g_vl[Bc*Hc*Tc*HSc];
__device__ float g_attn[NROW*Dc];
__device__ float g_res [NROW*Dc];

// ---------------- PTX helpers ----------------------------------------------
__device__ __forceinline__ uint32_t smem_u32(const void* p) {
    uint32_t a;
    asm("{ .reg .u64 t; cvta.to.shared.u64 t, %1; cvt.u32.u64 %0, t; }"
        : "=r"(a) : "l"(p));
    return a;
}
__device__ __forceinline__ void cp16(uint32_t s, const void* g) {
    asm volatile("cp.async.cg.shared.global [%0], [%1], 16;" :: "r"(s), "l"(g));
}
#define CP_COMMIT() asm volatile("cp.async.commit_group;" ::: "memory")
#define CP_WAIT(n)  asm volatile("cp.async.wait_group %0;" :: "n"(n) : "memory")

__device__ __forceinline__ void ldm4(uint32_t* r, uint32_t addr) {
    asm volatile("ldmatrix.sync.aligned.m8n8.x4.shared.b16 {%0,%1,%2,%3}, [%4];"
        : "=r"(r[0]), "=r"(r[1]), "=r"(r[2]), "=r"(r[3]) : "r"(addr));
}
__device__ __forceinline__ void ldm4t(uint32_t* r, uint32_t addr) {
    asm volatile("ldmatrix.sync.aligned.m8n8.x4.trans.shared.b16 {%0,%1,%2,%3}, [%4];"
        : "=r"(r[0]), "=r"(r[1]), "=r"(r[2]), "=r"(r[3]) : "r"(addr));
}
__device__ __forceinline__ void mma16816(float* d, const uint32_t* a, const uint32_t* b) {
    asm volatile("mma.sync.aligned.m16n8k16.row.col.f32.bf16.bf16.f32 "
        "{%0,%1,%2,%3}, {%4,%5,%6,%7}, {%8,%9}, {%0,%1,%2,%3};"
        : "+f"(d[0]), "+f"(d[1]), "+f"(d[2]), "+f"(d[3])
        : "r"(a[0]), "r"(a[1]), "r"(a[2]), "r"(a[3]), "r"(b[0]), "r"(b[1]));
}

__device__ __forceinline__ uint32_t pack_bf2(float a, float b) {
    __nv_bfloat162 h = __floats2bfloat162_rn(a, b);
    return *(uint32_t*)&h;
}
__device__ __forceinline__ uint32_t pack2h(__nv_bfloat16 a, __nv_bfloat16 b) {
    __nv_bfloat162 t; t.x = a; t.y = b;
    return *(uint32_t*)&t;
}
__device__ __forceinline__ void split1(float v, __nv_bfloat16& h, __nv_bfloat16& l) {
    h = __float2bfloat16_rn(v);
    l = __float2bfloat16_rn(v - __bfloat162float(h));
}

// ---------------------------------------------------------------------------
// LN kernels: write split bf16 hi/lo.
// ---------------------------------------------------------------------------
__device__ __forceinline__ void ln_body(float4 v, const float* gg, const float* bb,
                                        int base, __nv_bfloat16* dh, __nv_bfloat16* dl,
                                        size_t row)
{
    __shared__ float sbs[8], sbq[8];
    float s = v.x + v.y + v.z + v.w;
    float q = v.x*v.x + v.y*v.y + v.z*v.z + v.w*v.w;
#pragma unroll
    for (int o = 16; o; o >>= 1) {
        s += __shfl_xor_sync(0xffffffffu, s, o);
        q += __shfl_xor_sync(0xffffffffu, q, o);
    }
    if ((threadIdx.x & 31) == 0) { sbs[threadIdx.x >> 5] = s; sbq[threadIdx.x >> 5] = q; }
    __syncthreads();
    s = 0.f; q = 0.f;
#pragma unroll
    for (int i = 0; i < 8; i++) { s += sbs[i]; q += sbq[i]; }
    float mean = s * (1.f / Dc);
    float var  = q * (1.f / Dc) - mean * mean;
    float inv  = rsqrtf(var + EPSc);
    float4 g4 = *(const float4*)(gg + base);
    float4 b4 = *(const float4*)(bb + base);
    float o0 = (v.x - mean) * inv * g4.x + b4.x;
    float o1 = (v.y - mean) * inv * g4.y + b4.y;
    float o2 = (v.z - mean) * inv * g4.z + b4.z;
    float o3 = (v.w - mean) * inv * g4.w + b4.w;
    __nv_bfloat16 h0,h1,h2,h3,l0,l1,l2,l3;
    split1(o0,h0,l0); split1(o1,h1,l1); split1(o2,h2,l2); split1(o3,h3,l3);
    uint2 hp, lp;
    hp.x = pack2h(h0, h1); hp.y = pack2h(h2, h3);
    lp.x = pack2h(l0, l1); lp.y = pack2h(l2, l3);
    *(uint2*)(dh + row * Dc + base) = hp;
    *(uint2*)(dl + row * Dc + base) = lp;
}

__global__ void __launch_bounds__(256) ln1_kernel(const float* __restrict__ in,
                                                  const float* __restrict__ gg,
                                                  const float* __restrict__ bb)
{
    size_t row = blockIdx.x;
    int base = threadIdx.x * 4;
    float4 v = *(const float4*)(in + row * Dc + base);
    ln_body(v, gg, bb, base, g_xh, g_xl, row);
}

__global__ void __launch_bounds__(256) add_ln_kernel(const float* __restrict__ in,
                                                     const float* __restrict__ gg,
                                                     const float* __restrict__ bb)
{
    size_t row = blockIdx.x;
    int base = threadIdx.x * 4;
    float4 e = *(const float4*)(in     + row * Dc + base);
    float4 a = *(const float4*)(g_attn + row * Dc + base);
    float4 v = make_float4(e.x + a.x, e.y + a.y, e.z + a.z, e.w + a.w);
    *(float4*)(g_res + row * Dc + base) = v;
    ln_body(v, gg, bb, base, g_yh, g_yl, row);
}

// ---------------------------------------------------------------------------
// Weight transpose + split: dst[n*R + k] = split(src[k*C + n])
// ---------------------------------------------------------------------------
__global__ void __launch_bounds__(256) tsplit_kernel(const float* __restrict__ src,
                                                     __nv_bfloat16* __restrict__ dh,
                                                     __nv_bfloat16* __restrict__ dl,
                                                     int R, int C)
{
    __shared__ float t[32][33];
    int n0 = blockIdx.x * 32, k0 = blockIdx.y * 32;
    int tx = threadIdx.x, ty = threadIdx.y;
    for (int i = ty; i < 32; i += 8) t[i][tx] = src[(size_t)(k0 + i) * C + n0 + tx];
    __syncthreads();
    for (int i = ty; i < 32; i += 8) {
        float v = t[tx][i];
        __nv_bfloat16 h, l; split1(v, h, l);
        size_t o = (size_t)(n0 + i) * R + k0 + tx;
        dh[o] = h; dl[o] = l;
    }
}

__global__ void __launch_bounds__(256) qkv_tsplit_kernel(const float* __restrict__ Wq,
                                                         const float* __restrict__ Wk,
                                                         const float* __restrict__ Wv)
{
    __shared__ float t[32][33];
    int z = blockIdx.z;                    // 0..47
    int sel = z >> 4, h = z & 15;
    const float* src = (sel == 0 ? Wq : (sel == 1 ? Wk : Wv)) + (size_t)h * Dc * HSc;
    int n0 = blockIdx.x * 32, k0 = blockIdx.y * 32;
    int tx = threadIdx.x, ty = threadIdx.y;
    for (int i = ty; i < 32; i += 8) t[i][tx] = src[(size_t)(k0 + i) * HSc + n0 + tx];
    __syncthreads();
    for (int i = ty; i < 32; i += 8) {
        float v = t[tx][i];
        __nv_bfloat16 hh, ll; split1(v, hh, ll);
        size_t o = (size_t)(z * 64 + n0 + i) * Dc + k0 + tx;
        g_wqkvh[o] = hh; g_wqkvl[o] = ll;
    }
}

// ---------------------------------------------------------------------------
// Split-bf16 HMMA GEMM: C[128x128] = A[128xK] * B[128xK]^T, fp32 accum.
// 256 threads, 8 warps each 64x32. BK=32, cp.async 2-stage.
// mode 0: QKV -> split bf16 scatter; 1: relu(acc+b1) -> split bf16;
// 2: acc + b2 + res -> out.
// ---------------------------------------------------------------------------
#define STRIDEB 80
#define MATB    (128*STRIDEB)       // 10240
#define STGB    (4*MATB)            // 40960
#define GSM_TOTAL (2*STGB)          // 81920

__global__ void __launch_bounds__(256) gemm_mma_kernel(
    const __nv_bfloat16* __restrict__ Ah, const __nv_bfloat16* __restrict__ Al,
    const __nv_bfloat16* __restrict__ Bh, const __nv_bfloat16* __restrict__ Bl,
    int K, int mode, const float* __restrict__ bias, float* __restrict__ outF)
{
    extern __shared__ char smc[];
    uint32_t sb = smem_u32(smc);
    int tid = threadIdx.x, lane = tid & 31, w = tid >> 5;
    int m0 = (w & 1) * 64, n0w = (w >> 1) * 32;
    int mBase = blockIdx.x * 128, nBase = blockIdx.y * 128;
    int nc = K >> 5;

    float acc[4][4][4];
#pragma unroll
    for (int i = 0; i < 4; i++)
#pragma unroll
        for (int j = 0; j < 4; j++)
#pragma unroll
            for (int r = 0; r < 4; r++) acc[i][j][r] = 0.f;

    auto load_chunk = [&](int c, int buf) {
        int kcol = c << 5;
        uint32_t stg = sb + buf * STGB;
#pragma unroll
        for (int i = tid; i < 512; i += 256) {
            int r = i >> 2, sg = i & 3;
            uint32_t so = stg + r * STRIDEB + sg * 16;
            size_t ga = (size_t)(mBase + r) * K + kcol + sg * 8;
            size_t gb = (size_t)(nBase + r) * K + kcol + sg * 8;
            cp16(so,            Ah + ga);
            cp16(so + MATB,     Al + ga);
            cp16(so + 2*MATB,   Bh + gb);
            cp16(so + 3*MATB,   Bl + gb);
        }
        CP_COMMIT();
    };

    load_chunk(0, 0);

    for (int c = 0; c < nc; ++c) {
        if (c + 1 < nc) load_chunk(c + 1, (c + 1) & 1);
        if (c + 1 < nc) CP_WAIT(1); else CP_WAIT(0);
        __syncthreads();

        uint32_t stg = sb + (c & 1) * STGB;
#pragma unroll
        for (int ks = 0; ks < 2; ks++) {
            uint32_t colb = ks * 32 + (lane >> 4) * 16;
            uint32_t ah[4][4], al[4][4], bh[4][2], bl[4][2];
#pragma unroll
            for (int mi = 0; mi < 4; mi++) {
                uint32_t ro = (uint32_t)(m0 + mi * 16 + (lane & 15)) * STRIDEB + colb;
                ldm4(ah[mi], stg + ro);
                ldm4(al[mi], stg + MATB + ro);
            }
#pragma unroll
            for (int p = 0; p < 2; p++) {
                uint32_t ro = (uint32_t)(n0w + p * 16 + (lane & 15)) * STRIDEB + colb;
                uint32_t q[4];
                ldm4(q, stg + 2*MATB + ro);
                bh[2*p][0] = q[0]; bh[2*p][1] = q[2];
                bh[2*p+1][0] = q[1]; bh[2*p+1][1] = q[3];
                ldm4(q, stg + 3*MATB + ro);
                bl[2*p][0] = q[0]; bl[2*p][1] = q[2];
                bl[2*p+1][0] = q[1]; bl[2*p+1][1] = q[3];
            }
#pragma unroll
            for (int mi = 0; mi < 4; mi++)
#pragma unroll
                for (int nj = 0; nj < 4; nj++) {
                    mma16816(acc[mi][nj], ah[mi], bh[nj]);
                    mma16816(acc[mi][nj], ah[mi], bl[nj]);
                    mma16816(acc[mi][nj], al[mi], bh[nj]);
                }
        }
        __syncthreads();
    }

    // ---- epilogue: regs -> smem fp32 [128][132] -> fused global write ----
    float* Es = (float*)smc;
#pragma unroll
    for (int mi = 0; mi < 4; mi++)
#pragma unroll
        for (int nj = 0; nj < 4; nj++) {
            int r0 = m0 + mi * 16 + (lane >> 2);
            int c0 = n0w + nj * 8 + (lane & 3) * 2;
            Es[r0 * 132 + c0]           = acc[mi][nj][0];
            Es[r0 * 132 + c0 + 1]       = acc[mi][nj][1];
            Es[(r0 + 8) * 132 + c0]     = acc[mi][nj][2];
            Es[(r0 + 8) * 132 + c0 + 1] = acc[mi][nj][3];
        }
    __syncthreads();

    if (mode == 0) {            // QKV scatter -> split bf16 [bh][t][64]
        for (int idx = tid; idx < 1024; idx += 256) {
            int r = idx >> 3, seg = idx & 7;
            int m = mBase + r, bb2 = m >> 11, t = m & 2047;
            int nn = nBase + seg * 16;
            int sel = nn >> 10, rem = nn & 1023, h = rem >> 6, e = rem & 63;
            __nv_bfloat16* dh = (sel == 0 ? g_qh : (sel == 1 ? g_kh : g_vh));
            __nv_bfloat16* dl = (sel == 0 ? g_ql : (sel == 1 ? g_kl : g_vl));
            size_t o = (((size_t)(bb2 * Hc + h)) * Tc + t) * HSc + e;
            const float* es = &Es[r * 132 + seg * 16];
            uint32_t hp[8], lp[8];
#pragma unroll
            for (int jj = 0; jj < 8; jj++) {
                __nv_bfloat16 ha, la, hb, lb2;
                split1(es[2*jj],     ha, la);
                split1(es[2*jj + 1], hb, lb2);
                hp[jj] = pack2h(ha, hb); lp[jj] = pack2h(la, lb2);
            }
            *(uint4*)(dh + o)     = make_uint4(hp[0], hp[1], hp[2], hp[3]);
            *(uint4*)(dh + o + 8) = make_uint4(hp[4], hp[5], hp[6], hp[7]);
            *(uint4*)(dl + o)     = make_uint4(lp[0], lp[1], lp[2], lp[3]);
            *(uint4*)(dl + o + 8) = make_uint4(lp[4], lp[5], lp[6], lp[7]);
        }
    } else if (mode == 1) {     // FFN1: relu(acc+b1) -> split bf16
        for (int idx = tid; idx < 1024; idx += 256) {
            int r = idx >> 3, seg = idx & 7;
            int m = mBase + r;
            int nn = nBase + seg * 16;
            const float* es = &Es[r * 132 + seg * 16];
            uint32_t hp[8], lp[8];
#pragma unroll
            for (int jj = 0; jj < 8; jj++) {
                float a   = fmaxf(es[2*jj]   + bias[nn + 2*jj],     0.f);
                float b2v = fmaxf(es[2*jj+1] + bias[nn + 2*jj + 1], 0.f);
                __nv_bfloat16 ha, la, hb, lb2;
                split1(a, ha, la); split1(b2v, hb, lb2);
                hp[jj] = pack2h(ha, hb); lp[jj] = pack2h(la, lb2);
            }
            size_t o = (size_t)m * Fc + nn;
            *(uint4*)(g_ff1h + o)     = make_uint4(hp[0], hp[1], hp[2], hp[3]);
            *(uint4*)(g_ff1h + o + 8) = make_uint4(hp[4], hp[5], hp[6], hp[7]);
            *(uint4*)(g_ff1l + o)     = make_uint4(lp[0], lp[1], lp[2], lp[3]);
            *(uint4*)(g_ff1l + o + 8) = make_uint4(lp[4], lp[5], lp[6], lp[7]);
        }
    } else {                    // FFN2: acc + b2 + res -> out
        for (int idx = tid; idx < 1024; idx += 256) {
            int r = idx >> 3, seg = idx & 7;
            int m = mBase + r;
            int nn = nBase + seg * 16;
            const float* es = &Es[r * 132 + seg * 16];
            float* dst = outF + (size_t)m * Dc + nn;
            const float* res = g_res + (size_t)m * Dc + nn;
#pragma unroll
            for (int j = 0; j < 4; j++) {
                float4 rv = *(const float4*)(res + j * 4);
                float4 ov;
                ov.x = es[j*4]   + bias[nn + j*4]     + rv.x;
                ov.y = es[j*4+1] + bias[nn + j*4 + 1] + rv.y;
                ov.z = es[j*4+2] + bias[nn + j*4 + 2] + rv.z;
                ov.w = es[j*4+3] + bias[nn + j*4 + 3] + rv.w;
                *(float4*)(dst + j * 4) = ov;
            }
        }
    }
}

// ---------------------------------------------------------------------------
// HMMA flash attention, causal, split bf16. grid (T/128 [rev], B*H), 256 thr.
// Q-tile 128 (16 rows/warp), KV-tile 64, cp.async double buffer.
// smem: 2 bufs x 36864 B; buf = Kh(64x144) Kl Vh Vl; Q staged once in buf0.
// ---------------------------------------------------------------------------
#define AT_STR 144
#define AMAT   (64*AT_STR)      // 9216
#define ABUF   (4*AMAT)         // 36864
#define ASM_TOTAL (2*ABUF)      // 73728

__global__ void __launch_bounds__(256, 2) attn_mma_kernel()
{
    extern __shared__ char smc[];
    uint32_t sb = smem_u32(smc);
    int tid = threadIdx.x, lane = tid & 31, w = tid >> 5;
    int qt = (int)gridDim.x - 1 - (int)blockIdx.x;   // heavy CTAs first
    int bh = blockIdx.y;
    int qbase = qt * 128;

    const __nv_bfloat16* Qh = g_qh + (size_t)bh * Tc * HSc;
    const __nv_bfloat16* Ql = g_ql + (size_t)bh * Tc * HSc;
    const __nv_bfloat16* Kh = g_kh + (size_t)bh * Tc * HSc;
    const __nv_bfloat16* Kl = g_kl + (size_t)bh * Tc * HSc;
    const __nv_bfloat16* Vh = g_vh + (size_t)bh * Tc * HSc;
    const __nv_bfloat16* Vl = g_vl + (size_t)bh * Tc * HSc;

    // ---- stage Q (128 rows x 64), hi at 0, lo at 18432, load frags ----
    for (int i = tid; i < 1024; i += 256) {
        int r = i >> 3, ch = i & 7;
        uint32_t so = sb + r * AT_STR + ch * 16;
        size_t go = (size_t)(qbase + r) * HSc + ch * 8;
        cp16(so,          Qh + go);
        cp16(so + 2*AMAT, Ql + go);
    }
    CP_COMMIT(); CP_WAIT(0);
    __syncthreads();
    uint32_t qfh[4][4], qfl[4][4];
#pragma unroll
    for (int ks = 0; ks < 4; ks++) {
        uint32_t ro = (uint32_t)(w * 16 + (lane & 15)) * AT_STR + ks * 32 + (lane >> 4) * 16;
        ldm4(qfh[ks], sb + ro);
        ldm4(qfl[ks], sb + 2*AMAT + ro);
    }
    __syncthreads();

    float o[8][4];
#pragma unroll
    for (int i = 0; i < 8; i++)
#pragma unroll
        for (int j = 0; j < 4; j++) o[i][j] = 0.f;
    float m1 = -1e30f, m2 = -1e30f, l1 = 0.f, l2 = 0.f;
    int rg1 = qbase + w * 16 + (lane >> 2);
    int rg2 = rg1 + 8;

    auto loadKV = [&](int t, int buf) {
        uint32_t dst = sb + buf * ABUF;
#pragma unroll
        for (int i = tid; i < 512; i += 256) {
            int r = i >> 3, ch = i & 7;
            uint32_t so = dst + r * AT_STR + ch * 16;
            size_t go = (size_t)(t * 64 + r) * HSc + ch * 8;
            cp16(so,          Kh + go);
            cp16(so + AMAT,   Kl + go);
            cp16(so + 2*AMAT, Vh + go);
            cp16(so + 3*AMAT, Vl + go);
        }
        CP_COMMIT();
    };

    int ntiles = 2 * qt + 2;
    loadKV(0, 0);

    for (int t = 0; t < ntiles; t++) {
        if (t + 1 < ntiles) { loadKV(t + 1, (t + 1) & 1); CP_WAIT(1); }
        else                 CP_WAIT(0);
        __syncthreads();
        uint32_t bs = sb + (t & 1) * ABUF;

        // ---- S = Q K^T (split, 3 MMAs) ----
        float s[8][4];
#pragma unroll
        for (int i = 0; i < 8; i++)
#pragma unroll
            for (int j = 0; j < 4; j++) s[i][j] = 0.f;
#pragma unroll
        for (int ks = 0; ks < 4; ks++) {
#pragma unroll
            for (int p = 0; p < 4; p++) {
                uint32_t ro = (uint32_t)(p * 16 + (lane & 15)) * AT_STR + ks * 32 + (lane >> 4) * 16;
                uint32_t qa[4], qb[4];
                ldm4(qa, bs + ro);          // Kh
                ldm4(qb, bs + AMAT + ro);   // Kl
                uint32_t b0h[2] = {qa[0], qa[2]}, b1h[2] = {qa[1], qa[3]};
                uint32_t b0l[2] = {qb[0], qb[2]}, b1l[2] = {qb[1], qb[3]};
                mma16816(s[2*p],   qfh[ks], b0h);
                mma16816(s[2*p],   qfl[ks], b0h);
                mma16816(s[2*p],   qfh[ks], b0l);
                mma16816(s[2*p+1], qfh[ks], b1h);
                mma16816(s[2*p+1], qfl[ks], b1h);
                mma16816(s[2*p+1], qfh[ks], b1l);
            }
        }

        // ---- scale, mask, online softmax ----
        bool diag = (t >= 2 * qt);
        int kvb = t * 64;
        float mx1 = -1e30f, mx2 = -1e30f;
#pragma unroll
        for (int nj = 0; nj < 8; nj++) {
            int cb = kvb + nj * 8 + (lane & 3) * 2;
            float v0 = s[nj][0] * 0.03125f;
            float v1 = s[nj][1] * 0.03125f;
            float v2 = s[nj][2] * 0.03125f;
            float v3 = s[nj][3] * 0.03125f;
            if (diag) {
                if (cb     > rg1) v0 = -1e30f;
                if (cb + 1 > rg1) v1 = -1e30f;
                if (cb     > rg2) v2 = -1e30f;
                if (cb + 1 > rg2) v3 = -1e30f;
            }
            s[nj][0] = v0; s[nj][1] = v1; s[nj][2] = v2; s[nj][3] = v3;
            mx1 = fmaxf(mx1, fmaxf(v0, v1));
            mx2 = fmaxf(mx2, fmaxf(v2, v3));
        }
        mx1 = fmaxf(mx1, __shfl_xor_sync(0xffffffffu, mx1, 1));
        mx1 = fmaxf(mx1, __shfl_xor_sync(0xffffffffu, mx1, 2));
        mx2 = fmaxf(mx2, __shfl_xor_sync(0xffffffffu, mx2, 1));
        mx2 = fmaxf(mx2, __shfl_xor_sync(0xffffffffu, mx2, 2));
        float mn1 = fmaxf(m1, mx1), mn2 = fmaxf(m2, mx2);
        float sc1 = __expf(m1 - mn1), sc2 = __expf(m2 - mn2);
        float ls1 = 0.f, ls2 = 0.f;
#pragma unroll
        for (int nj = 0; nj < 8; nj++) {
            s[nj][0] = __expf(s[nj][0] - mn1);
            s[nj][1] = __expf(s[nj][1] - mn1);
            s[nj][2] = __expf(s[nj][2] - mn2);
            s[nj][3] = __expf(s[nj][3] - mn2);
            ls1 += s[nj][0] + s[nj][1];
            ls2 += s[nj][2] + s[nj][3];
        }
        ls1 += __shfl_xor_sync(0xffffffffu, ls1, 1);
        ls1 += __shfl_xor_sync(0xffffffffu, ls1, 2);
        ls2 += __shfl_xor_sync(0xffffffffu, ls2, 1);
        ls2 += __shfl_xor_sync(0xffffffffu, ls2, 2);
        l1 = l1 * sc1 + ls1;  m1 = mn1;
        l2 = l2 * sc2 + ls2;  m2 = mn2;
#pragma unroll
        for (int nj = 0; nj < 8; nj++) {
            o[nj][0] *= sc1; o[nj][1] *= sc1;
            o[nj][2] *= sc2; o[nj][3] *= sc2;
        }

        // ---- PV (split P and V, 3 MMAs) ----
#pragma unroll
        for (int kp = 0; kp < 4; kp++) {
            uint32_t pah[4], pal[4];
            {
                __nv_bfloat16 h0,h1,h2,h3,l0x,l1x,l2x,l3x;
                split1(s[2*kp][0], h0, l0x); split1(s[2*kp][1], h1, l1x);
                split1(s[2*kp][2], h2, l2x); split1(s[2*kp][3], h3, l3x);
                pah[0] = pack2h(h0, h1); pah[1] = pack2h(h2, h3);
                pal[0] = pack2h(l0x, l1x); pal[1] = pack2h(l2x, l3x);
                split1(s[2*kp+1][0], h0, l0x); split1(s[2*kp+1][1], h1, l1x);
                split1(s[2*kp+1][2], h2, l2x); split1(s[2*kp+1][3], h3, l3x);
                pah[2] = pack2h(h0, h1); pah[3] = pack2h(h2, h3);
                pal[2] = pack2h(l0x, l1x); pal[3] = pack2h(l2x, l3x);
            }
#pragma unroll
            for (int pd = 0; pd < 4; pd++) {
                uint32_t ro = (uint32_t)(kp * 16 + (lane & 15)) * AT_STR + pd * 32 + (lane >> 4) * 16;
                uint32_t qa[4], qb[4];
                ldm4t(qa, bs + 2*AMAT + ro);   // Vh (transposed)
                ldm4t(qb, bs + 3*AMAT + ro);   // Vl
                uint32_t b0h[2] = {qa[0], qa[1]}, b1h[2] = {qa[2], qa[3]};
                uint32_t b0l[2] = {qb[0], qb[1]}, b1l[2] = {qb[2], qb[3]};
                mma16816(o[2*pd],   pah, b0h);
                mma16816(o[2*pd],   pal, b0h);
                mma16816(o[2*pd],   pah, b0l);
                mma16816(o[2*pd+1], pah, b1h);
                mma16816(o[2*pd+1], pal, b1h);
                mma16816(o[2*pd+1], pah, b1l);
            }
        }
        __syncthreads();
    }

    // ---- epilogue: 1/l, stage smem, coalesced write ----
    float i1 = 1.f / l1, i2 = 1.f / l2;
    float* Os = (float*)smc;     // [128][68]
    int r1 = w * 16 + (lane >> 2), r2 = r1 + 8;
#pragma unroll
    for (int nj = 0; nj < 8; nj++) {
        int c0 = nj * 8 + (lane & 3) * 2;
        Os[r1 * 68 + c0]     = o[nj][0] * i1;
        Os[r1 * 68 + c0 + 1] = o[nj][1] * i1;
        Os[r2 * 68 + c0]     = o[nj][2] * i2;
        Os[r2 * 68 + c0 + 1] = o[nj][3] * i2;
    }
    __syncthreads();
    int b = bh >> 4, h = bh & 15;
    for (int i = tid; i < 2048; i += 256) {
        int r = i >> 4, cq = (i & 15) * 4;
        float4 v = *(const float4*)&Os[r * 68 + cq];
        *(float4*)(g_attn + ((size_t)b * Tc + qbase + r) * Dc + h * HSc + cq) = v;
    }
}

// ---------------------------------------------------------------------------
extern "C" void kernel_launch(void* const* d_in, const int* in_sizes, int n_in,
                              void* d_out, int out_size)
{
    (void)in_sizes; (void)n_in; (void)out_size;
    const float* embds = (const float*)d_in[0];
    const float* Wq    = (const float*)d_in[1];
    const float* Wk    = (const float*)d_in[2];
    const float* Wv    = (const float*)d_in[3];
    const float* ln1_g = (const float*)d_in[4];
    const float* ln1_b = (const float*)d_in[5];
    const float* ln2_g = (const float*)d_in[6];
    const float* ln2_b = (const float*)d_in[7];
    const float* W1    = (const float*)d_in[8];
    const float* b1    = (const float*)d_in[9];
    const float* W2    = (const float*)d_in[10];
    const float* b2    = (const float*)d_in[11];
    float* out = (float*)d_out;

    cudaFuncSetAttribute(attn_mma_kernel, cudaFuncAttributeMaxDynamicSharedMemorySize,
                         ASM_TOTAL);
    cudaFuncSetAttribute(gemm_mma_kernel, cudaFuncAttributeMaxDynamicSharedMemorySize,
                         GSM_TOTAL);

    __nv_bfloat16 *xh, *xl, *yh, *yl, *wqh, *wql, *w1h, *w1l, *w2h, *w2l, *f1h, *f1l;
    cudaGetSymbolAddress((void**)&xh, g_xh);   cudaGetSymbolAddress((void**)&xl, g_xl);
    cudaGetSymbolAddress((void**)&yh, g_yh);   cudaGetSymbolAddress((void**)&yl, g_yl);
    cudaGetSymbolAddress((void**)&wqh, g_wqkvh); cudaGetSymbolAddress((void**)&wql, g_wqkvl);
    cudaGetSymbolAddress((void**)&w1h, g_w1h); cudaGetSymbolAddress((void**)&w1l, g_w1l);
    cudaGetSymbolAddress((void**)&w2h, g_w2h); cudaGetSymbolAddress((void**)&w2l, g_w2l);
    cudaGetSymbolAddress((void**)&f1h, g_ff1h); cudaGetSymbolAddress((void**)&f1l, g_ff1l);

    ln1_kernel<<<NROW, 256>>>(embds, ln1_g, ln1_b);
    qkv_tsplit_kernel<<<dim3(2, 32, 48), dim3(32, 8)>>>(Wq, Wk, Wv);
    tsplit_kernel<<<dim3(128, 32), dim3(32, 8)>>>(W1, w1h, w1l, Dc, Fc);
    tsplit_kernel<<<dim3(32, 128), dim3(32, 8)>>>(W2, w2h, w2l, Fc, Dc);

    // QKV: A = x split [4096,1024], B = wqkv [3072,1024]
    gemm_mma_kernel<<<dim3(32, 24), 256, GSM_TOTAL>>>(xh, xl, wqh, wql,
                                                      Dc, 0, nullptr, nullptr);
    attn_mma_kernel<<<dim3(Tc / 128, Bc * Hc), 256, ASM_TOTAL>>>();
    add_ln_kernel<<<NROW, 256>>>(embds, ln2_g, ln2_b);
    // FFN1: A = y [4096,1024], B = w1t [4096,1024]
    gemm_mma_kernel<<<dim3(32, 32), 256, GSM_TOTAL>>>(yh, yl, w1h, w1l,
                                                      Dc, 1, b1, nullptr);
    // FFN2: A = ff1 [4096,4096], B = w2t [1024,4096]
    gemm_mma_kernel<<<dim3(32, 8), 256, GSM_TOTAL>>>(f1h, f1l, w2h, w2l,
                                                     Fc, 2, b2, out);
}

// round 6
// speedup vs baseline: 6.5880x; 1.3344x over previous
#include <cuda_runtime.h>
#include <cuda_fp16.h>
#include <cstdint>

// ---------------------------------------------------------------------------
// Transformer block. B=2, T=2048, D=1024, H=16, HS=64, FF=4096
// All matmuls on mma.sync fp16 (one operand split hi/lo, 2-MMA fp32 emu).
// ---------------------------------------------------------------------------

#define Bc   2
#define Tc   2048
#define Dc   1024
#define Hc   16
#define HSc  64
#define Fc   4096
#define EPSc 1e-5f
#define NROW (Bc*Tc)            // 4096 rows

// ---------------- scratch (device globals; allocation-free rule) -----------
__device__ __half g_x  [NROW*Dc];            // LN1 out (single fp16)
__device__ __half g_y  [NROW*Dc];            // LN2 out
__device__ __half g_wqkvh[3*Dc*Dc];          // [3072 n, 1024 k] W^T hi
__device__ __half g_wqkvl[3*Dc*Dc];          // lo
__device__ __half g_w1h[Fc*Dc];              // W1^T [4096,1024]
__device__ __half g_w1l[Fc*Dc];
__device__ __half g_w2h[Dc*Fc];              // W2^T [1024,4096]
__device__ __half g_w2l[Dc*Fc];
__device__ __half g_ff1[(size_t)NROW*Fc];    // relu(y W1 + b1), single fp16
__device__ __half g_qh[Bc*Hc*Tc*HSc];        // Q split
__device__ __half g_ql[Bc*Hc*Tc*HSc];
__device__ __half g_k [Bc*Hc*Tc*HSc];        // K single
__device__ __half g_v [Bc*Hc*Tc*HSc];        // V single
__device__ float g_attn[NROW*Dc];
__device__ float g_res [NROW*Dc];

// ---------------- PTX helpers ----------------------------------------------
__device__ __forceinline__ uint32_t smem_u32(const void* p) {
    uint32_t a;
    asm("{ .reg .u64 t; cvta.to.shared.u64 t, %1; cvt.u32.u64 %0, t; }"
        : "=r"(a) : "l"(p));
    return a;
}
__device__ __forceinline__ void cp16(uint32_t s, const void* g) {
    asm volatile("cp.async.cg.shared.global [%0], [%1], 16;" :: "r"(s), "l"(g));
}
#define CP_COMMIT() asm volatile("cp.async.commit_group;" ::: "memory")
#define CP_WAIT(n)  asm volatile("cp.async.wait_group %0;" :: "n"(n) : "memory")

__device__ __forceinline__ void ldm4(uint32_t* r, uint32_t addr) {
    asm volatile("ldmatrix.sync.aligned.m8n8.x4.shared.b16 {%0,%1,%2,%3}, [%4];"
        : "=r"(r[0]), "=r"(r[1]), "=r"(r[2]), "=r"(r[3]) : "r"(addr));
}
__device__ __forceinline__ void ldm4t(uint32_t* r, uint32_t addr) {
    asm volatile("ldmatrix.sync.aligned.m8n8.x4.trans.shared.b16 {%0,%1,%2,%3}, [%4];"
        : "=r"(r[0]), "=r"(r[1]), "=r"(r[2]), "=r"(r[3]) : "r"(addr));
}
__device__ __forceinline__ void mma16816(float* d, const uint32_t* a, const uint32_t* b) {
    asm volatile("mma.sync.aligned.m16n8k16.row.col.f32.f16.f16.f32 "
        "{%0,%1,%2,%3}, {%4,%5,%6,%7}, {%8,%9}, {%0,%1,%2,%3};"
        : "+f"(d[0]), "+f"(d[1]), "+f"(d[2]), "+f"(d[3])
        : "r"(a[0]), "r"(a[1]), "r"(a[2]), "r"(a[3]), "r"(b[0]), "r"(b[1]));
}

__device__ __forceinline__ uint32_t pack2hf(__half a, __half b) {
    __half2 t; t.x = a; t.y = b;
    return *(uint32_t*)&t;
}
__device__ __forceinline__ void split1h(float v, __half& h, __half& l) {
    h = __float2half_rn(v);
    l = __float2half_rn(v - __half2float(h));
}

// ---------------------------------------------------------------------------
// LN kernels: write single fp16.
// ---------------------------------------------------------------------------
__device__ __forceinline__ void ln_body(float4 v, const float* gg, const float* bb,
                                        int base, __half* dst, size_t row)
{
    __shared__ float sbs[8], sbq[8];
    float s = v.x + v.y + v.z + v.w;
    float q = v.x*v.x + v.y*v.y + v.z*v.z + v.w*v.w;
#pragma unroll
    for (int o = 16; o; o >>= 1) {
        s += __shfl_xor_sync(0xffffffffu, s, o);
        q += __shfl_xor_sync(0xffffffffu, q, o);
    }
    if ((threadIdx.x & 31) == 0) { sbs[threadIdx.x >> 5] = s; sbq[threadIdx.x >> 5] = q; }
    __syncthreads();
    s = 0.f; q = 0.f;
#pragma unroll
    for (int i = 0; i < 8; i++) { s += sbs[i]; q += sbq[i]; }
    float mean = s * (1.f / Dc);
    float var  = q * (1.f / Dc) - mean * mean;
    float inv  = rsqrtf(var + EPSc);
    float4 g4 = *(const float4*)(gg + base);
    float4 b4 = *(const float4*)(bb + base);
    uint2 o;
    o.x = pack2hf(__float2half_rn((v.x - mean) * inv * g4.x + b4.x),
                  __float2half_rn((v.y - mean) * inv * g4.y + b4.y));
    o.y = pack2hf(__float2half_rn((v.z - mean) * inv * g4.z + b4.z),
                  __float2half_rn((v.w - mean) * inv * g4.w + b4.w));
    *(uint2*)(dst + row * Dc + base) = o;
}

__global__ void __launch_bounds__(256) ln1_kernel(const float* __restrict__ in,
                                                  const float* __restrict__ gg,
                                                  const float* __restrict__ bb)
{
    size_t row = blockIdx.x;
    int base = threadIdx.x * 4;
    float4 v = *(const float4*)(in + row * Dc + base);
    ln_body(v, gg, bb, base, g_x, row);
}

__global__ void __launch_bounds__(256) add_ln_kernel(const float* __restrict__ in,
                                                     const float* __restrict__ gg,
                                                     const float* __restrict__ bb)
{
    size_t row = blockIdx.x;
    int base = threadIdx.x * 4;
    float4 e = *(const float4*)(in     + row * Dc + base);
    float4 a = *(const float4*)(g_attn + row * Dc + base);
    float4 v = make_float4(e.x + a.x, e.y + a.y, e.z + a.z, e.w + a.w);
    *(float4*)(g_res + row * Dc + base) = v;
    ln_body(v, gg, bb, base, g_y, row);
}

// ---------------------------------------------------------------------------
// Weight transpose + split (fp16 hi/lo): dst[n*R + k] = split(src[k*C + n])
// ---------------------------------------------------------------------------
__global__ void __launch_bounds__(256) tsplit_kernel(const float* __restrict__ src,
                                                     __half* __restrict__ dh,
                                                     __half* __restrict__ dl,
                                                     int R, int C)
{
    __shared__ float t[32][33];
    int n0 = blockIdx.x * 32, k0 = blockIdx.y * 32;
    int tx = threadIdx.x, ty = threadIdx.y;
    for (int i = ty; i < 32; i += 8) t[i][tx] = src[(size_t)(k0 + i) * C + n0 + tx];
    __syncthreads();
    for (int i = ty; i < 32; i += 8) {
        float v = t[tx][i];
        __half h, l; split1h(v, h, l);
        size_t o = (size_t)(n0 + i) * R + k0 + tx;
        dh[o] = h; dl[o] = l;
    }
}

__global__ void __launch_bounds__(256) qkv_tsplit_kernel(const float* __restrict__ Wq,
                                                         const float* __restrict__ Wk,
                                                         const float* __restrict__ Wv)
{
    __shared__ float t[32][33];
    int z = blockIdx.z;                    // 0..47
    int sel = z >> 4, h = z & 15;
    const float* src = (sel == 0 ? Wq : (sel == 1 ? Wk : Wv)) + (size_t)h * Dc * HSc;
    int n0 = blockIdx.x * 32, k0 = blockIdx.y * 32;
    int tx = threadIdx.x, ty = threadIdx.y;
    for (int i = ty; i < 32; i += 8) t[i][tx] = src[(size_t)(k0 + i) * HSc + n0 + tx];
    __syncthreads();
    for (int i = ty; i < 32; i += 8) {
        float v = t[tx][i];
        __half hh, ll; split1h(v, hh, ll);
        size_t o = (size_t)(z * 64 + n0 + i) * Dc + k0 + tx;
        g_wqkvh[o] = hh; g_wqkvl[o] = ll;
    }
}

// ---------------------------------------------------------------------------
// fp16 2-MMA GEMM: C[256x128] = A[256xK] * B[128xK]^T, fp32 accum.
// A single fp16, B split hi/lo. 256 threads, 8 warps (4x2), warp tile 64x64.
// BK=32, cp.async double buffer. Epilogue staged in two 128-row halves.
// mode 0: QKV (q split, k/v single fp16); 1: relu(acc+b1) -> fp16 ff1;
// 2: acc + b2 + res -> out fp32.
// ---------------------------------------------------------------------------
#define GSTR 80
#define BHOFF (256*GSTR)            // 20480
#define BLOFF (BHOFF + 128*GSTR)    // 30720
#define STGB  (BLOFF + 128*GSTR)    // 40960
#define GSM_TOTAL (2*STGB)          // 81920

__global__ void __launch_bounds__(256) gemm_mma_kernel(
    const __half* __restrict__ A,
    const __half* __restrict__ Bh, const __half* __restrict__ Bl,
    int K, int mode, const float* __restrict__ bias, float* __restrict__ outF)
{
    extern __shared__ char smc[];
    uint32_t sb = smem_u32(smc);
    int tid = threadIdx.x, lane = tid & 31, w = tid >> 5;
    int wm = w >> 1, wn = w & 1;              // warp tile (64 rows, 64 cols)
    int mBase = blockIdx.x * 256, nBase = blockIdx.y * 128;
    int nc = K >> 5;

    float acc[4][8][4];
#pragma unroll
    for (int i = 0; i < 4; i++)
#pragma unroll
        for (int j = 0; j < 8; j++)
#pragma unroll
            for (int r = 0; r < 4; r++) acc[i][j][r] = 0.f;

    auto load_chunk = [&](int c, int buf) {
        int kcol = c << 5;
        uint32_t stg = sb + buf * STGB;
        for (int i = tid; i < 1024; i += 256) {           // A: 256 rows
            int r = i >> 2, sg = i & 3;
            cp16(stg + r * GSTR + sg * 16,
                 A + (size_t)(mBase + r) * K + kcol + sg * 8);
        }
        for (int i = tid; i < 512; i += 256) {            // B hi/lo: 128 rows
            int r = i >> 2, sg = i & 3;
            size_t gb = (size_t)(nBase + r) * K + kcol + sg * 8;
            uint32_t so = r * GSTR + sg * 16;
            cp16(stg + BHOFF + so, Bh + gb);
            cp16(stg + BLOFF + so, Bl + gb);
        }
        CP_COMMIT();
    };

    load_chunk(0, 0);

    for (int c = 0; c < nc; ++c) {
        if (c + 1 < nc) { load_chunk(c + 1, (c + 1) & 1); CP_WAIT(1); }
        else             CP_WAIT(0);
        __syncthreads();

        uint32_t stg = sb + (c & 1) * STGB;
#pragma unroll
        for (int ks = 0; ks < 2; ks++) {
            uint32_t colb = ks * 32 + (lane >> 4) * 16;
            uint32_t af[4][4], bh[8][2], bl[8][2];
#pragma unroll
            for (int mi = 0; mi < 4; mi++) {
                uint32_t ro = (uint32_t)(wm * 64 + mi * 16 + (lane & 15)) * GSTR + colb;
                ldm4(af[mi], stg + ro);
            }
#pragma unroll
            for (int p = 0; p < 4; p++) {
                uint32_t ro = (uint32_t)(wn * 64 + p * 16 + (lane & 15)) * GSTR + colb;
                uint32_t q[4];
                ldm4(q, stg + BHOFF + ro);
                bh[2*p][0] = q[0]; bh[2*p][1] = q[2];
                bh[2*p+1][0] = q[1]; bh[2*p+1][1] = q[3];
                ldm4(q, stg + BLOFF + ro);
                bl[2*p][0] = q[0]; bl[2*p][1] = q[2];
                bl[2*p+1][0] = q[1]; bl[2*p+1][1] = q[3];
            }
#pragma unroll
            for (int mi = 0; mi < 4; mi++)
#pragma unroll
                for (int nj = 0; nj < 8; nj++) {
                    mma16816(acc[mi][nj], af[mi], bh[nj]);
                    mma16816(acc[mi][nj], af[mi], bl[nj]);
                }
        }
        __syncthreads();
    }

    // ---- epilogue: two 128-row halves through smem [128][132] ----
    float* Es = (float*)smc;
    for (int ph = 0; ph < 2; ph++) {
        __syncthreads();
        if ((wm >> 1) == ph) {
            int rl = (wm & 1) * 64;
#pragma unroll
            for (int mi = 0; mi < 4; mi++)
#pragma unroll
                for (int nj = 0; nj < 8; nj++) {
                    int r0 = rl + mi * 16 + (lane >> 2);
                    int c0 = wn * 64 + nj * 8 + (lane & 3) * 2;
                    Es[r0 * 132 + c0]           = acc[mi][nj][0];
                    Es[r0 * 132 + c0 + 1]       = acc[mi][nj][1];
                    Es[(r0 + 8) * 132 + c0]     = acc[mi][nj][2];
                    Es[(r0 + 8) * 132 + c0 + 1] = acc[mi][nj][3];
                }
        }
        __syncthreads();

        if (mode == 0) {            // QKV: q split fp16, k/v single fp16
            for (int idx = tid; idx < 1024; idx += 256) {
                int r = idx >> 3, seg = idx & 7;
                int m = mBase + ph * 128 + r, bb2 = m >> 11, t = m & 2047;
                int nn = nBase + seg * 16;
                int sel = nn >> 10, rem = nn & 1023, h = rem >> 6, e = rem & 63;
                size_t o = (((size_t)(bb2 * Hc + h)) * Tc + t) * HSc + e;
                const float* es = &Es[r * 132 + seg * 16];
                if (sel == 0) {
                    uint32_t hp[8], lp[8];
#pragma unroll
                    for (int jj = 0; jj < 8; jj++) {
                        __half ha, la, hb, lb2;
                        split1h(es[2*jj],     ha, la);
                        split1h(es[2*jj + 1], hb, lb2);
                        hp[jj] = pack2hf(ha, hb); lp[jj] = pack2hf(la, lb2);
                    }
                    *(uint4*)(g_qh + o)     = make_uint4(hp[0], hp[1], hp[2], hp[3]);
                    *(uint4*)(g_qh + o + 8) = make_uint4(hp[4], hp[5], hp[6], hp[7]);
                    *(uint4*)(g_ql + o)     = make_uint4(lp[0], lp[1], lp[2], lp[3]);
                    *(uint4*)(g_ql + o + 8) = make_uint4(lp[4], lp[5], lp[6], lp[7]);
                } else {
                    __half* dst = (sel == 1) ? g_k : g_v;
                    uint32_t hp[8];
#pragma unroll
                    for (int jj = 0; jj < 8; jj++)
                        hp[jj] = pack2hf(__float2half_rn(es[2*jj]),
                                         __float2half_rn(es[2*jj + 1]));
                    *(uint4*)(dst + o)     = make_uint4(hp[0], hp[1], hp[2], hp[3]);
                    *(uint4*)(dst + o + 8) = make_uint4(hp[4], hp[5], hp[6], hp[7]);
                }
            }
        } else if (mode == 1) {     // FFN1: relu(acc+b1) -> single fp16
            for (int idx = tid; idx < 1024; idx += 256) {
                int r = idx >> 3, seg = idx & 7;
                int m = mBase + ph * 128 + r;
                int nn = nBase + seg * 16;
                const float* es = &Es[r * 132 + seg * 16];
                uint32_t hp[8];
#pragma unroll
                for (int jj = 0; jj < 8; jj++) {
                    float a   = fmaxf(es[2*jj]   + bias[nn + 2*jj],     0.f);
                    float b2v = fmaxf(es[2*jj+1] + bias[nn + 2*jj + 1], 0.f);
                    hp[jj] = pack2hf(__float2half_rn(a), __float2half_rn(b2v));
                }
                size_t o = (size_t)m * Fc + nn;
                *(uint4*)(g_ff1 + o)     = make_uint4(hp[0], hp[1], hp[2], hp[3]);
                *(uint4*)(g_ff1 + o + 8) = make_uint4(hp[4], hp[5], hp[6], hp[7]);
            }
        } else {                    // FFN2: acc + b2 + res -> out fp32
            for (int idx = tid; idx < 1024; idx += 256) {
                int r = idx >> 3, seg = idx & 7;
                int m = mBase + ph * 128 + r;
                int nn = nBase + seg * 16;
                const float* es = &Es[r * 132 + seg * 16];
                float* dst = outF + (size_t)m * Dc + nn;
                const float* res = g_res + (size_t)m * Dc + nn;
#pragma unroll
                for (int j = 0; j < 4; j++) {
                    float4 rv = *(const float4*)(res + j * 4);
                    float4 ov;
                    ov.x = es[j*4]   + bias[nn + j*4]     + rv.x;
                    ov.y = es[j*4+1] + bias[nn + j*4 + 1] + rv.y;
                    ov.z = es[j*4+2] + bias[nn + j*4 + 2] + rv.z;
                    ov.w = es[j*4+3] + bias[nn + j*4 + 3] + rv.w;
                    *(float4*)(dst + j * 4) = ov;
                }
            }
        }
    }
}

// ---------------------------------------------------------------------------
// fp16 flash attention, causal. grid (T/128 [rev], B*H), 256 threads.
// Q split (2-MMA S), K single; P split (2-MMA PV), V single.
// smem: Q staged (hi + lo), then 2 KV buffers of (K + V) = 18432 B each.
// ---------------------------------------------------------------------------
#define AT_STR 144
#define AMAT   (64*AT_STR)      // 9216
#define ABUF   (2*AMAT)         // 18432
#define ASM_TOTAL (2*ABUF)      // 36864

__global__ void __launch_bounds__(256, 2) attn_mma_kernel()
{
    extern __shared__ char smc[];
    uint32_t sb = smem_u32(smc);
    int tid = threadIdx.x, lane = tid & 31, w = tid >> 5;
    int qt = (int)gridDim.x - 1 - (int)blockIdx.x;   // heavy CTAs first
    int bh = blockIdx.y;
    int qbase = qt * 128;

    const __half* Qh = g_qh + (size_t)bh * Tc * HSc;
    const __half* Ql = g_ql + (size_t)bh * Tc * HSc;
    const __half* Kp = g_k  + (size_t)bh * Tc * HSc;
    const __half* Vp = g_v  + (size_t)bh * Tc * HSc;

    // ---- stage Q (128 rows x 64): hi at 0, lo at ABUF; extract frags ----
    for (int i = tid; i < 1024; i += 256) {
        int r = i >> 3, ch = i & 7;
        uint32_t so = sb + r * AT_STR + ch * 16;
        size_t go = (size_t)(qbase + r) * HSc + ch * 8;
        cp16(so,        Qh + go);
        cp16(so + ABUF, Ql + go);
    }
    CP_COMMIT(); CP_WAIT(0);
    __syncthreads();
    uint32_t qfh[4][4], qfl[4][4];
#pragma unroll
    for (int ks = 0; ks < 4; ks++) {
        uint32_t ro = (uint32_t)(w * 16 + (lane & 15)) * AT_STR + ks * 32 + (lane >> 4) * 16;
        ldm4(qfh[ks], sb + ro);
        ldm4(qfl[ks], sb + ABUF + ro);
    }
    __syncthreads();

    float o[8][4];
#pragma unroll
    for (int i = 0; i < 8; i++)
#pragma unroll
        for (int j = 0; j < 4; j++) o[i][j] = 0.f;
    float m1 = -1e30f, m2 = -1e30f, l1 = 0.f, l2 = 0.f;
    int rg1 = qbase + w * 16 + (lane >> 2);
    int rg2 = rg1 + 8;

    // FIX (R6): full 128-byte rows for both K and V -> 1024 chunk copies.
    auto loadKV = [&](int t, int buf) {
        uint32_t dst = sb + buf * ABUF;
        for (int i = tid; i < 1024; i += 256) {
            int mat = i >> 9, r = (i & 511) >> 3, ch = i & 7;
            uint32_t so = dst + mat * AMAT + r * AT_STR + ch * 16;
            size_t go = (size_t)(t * 64 + r) * HSc + ch * 8;
            cp16(so, (mat == 0 ? Kp : Vp) + go);
        }
        CP_COMMIT();
    };

    int ntiles = 2 * qt + 2;
    loadKV(0, 0);

    for (int t = 0; t < ntiles; t++) {
        if (t + 1 < ntiles) { loadKV(t + 1, (t + 1) & 1); CP_WAIT(1); }
        else                 CP_WAIT(0);
        __syncthreads();
        uint32_t bs = sb + (t & 1) * ABUF;

        // ---- S = Q K^T (Q split, 2 MMAs) ----
        float s[8][4];
#pragma unroll
        for (int i = 0; i < 8; i++)
#pragma unroll
            for (int j = 0; j < 4; j++) s[i][j] = 0.f;
#pragma unroll
        for (int ks = 0; ks < 4; ks++) {
#pragma unroll
            for (int p = 0; p < 4; p++) {
                uint32_t ro = (uint32_t)(p * 16 + (lane & 15)) * AT_STR + ks * 32 + (lane >> 4) * 16;
                uint32_t qa[4];
                ldm4(qa, bs + ro);          // K
                uint32_t b0[2] = {qa[0], qa[2]}, b1[2] = {qa[1], qa[3]};
                mma16816(s[2*p],   qfh[ks], b0);
                mma16816(s[2*p],   qfl[ks], b0);
                mma16816(s[2*p+1], qfh[ks], b1);
                mma16816(s[2*p+1], qfl[ks], b1);
            }
        }

        // ---- scale, mask, online softmax ----
        bool diag = (t >= 2 * qt);
        int kvb = t * 64;
        float mx1 = -1e30f, mx2 = -1e30f;
#pragma unroll
        for (int nj = 0; nj < 8; nj++) {
            int cb = kvb + nj * 8 + (lane & 3) * 2;
            float v0 = s[nj][0] * 0.03125f;
            float v1 = s[nj][1] * 0.03125f;
            float v2 = s[nj][2] * 0.03125f;
            float v3 = s[nj][3] * 0.03125f;
            if (diag) {
                if (cb     > rg1) v0 = -1e30f;
                if (cb + 1 > rg1) v1 = -1e30f;
                if (cb     > rg2) v2 = -1e30f;
                if (cb + 1 > rg2) v3 = -1e30f;
            }
            s[nj][0] = v0; s[nj][1] = v1; s[nj][2] = v2; s[nj][3] = v3;
            mx1 = fmaxf(mx1, fmaxf(v0, v1));
            mx2 = fmaxf(mx2, fmaxf(v2, v3));
        }
        mx1 = fmaxf(mx1, __shfl_xor_sync(0xffffffffu, mx1, 1));
        mx1 = fmaxf(mx1, __shfl_xor_sync(0xffffffffu, mx1, 2));
        mx2 = fmaxf(mx2, __shfl_xor_sync(0xffffffffu, mx2, 1));
        mx2 = fmaxf(mx2, __shfl_xor_sync(0xffffffffu, mx2, 2));
        float mn1 = fmaxf(m1, mx1), mn2 = fmaxf(m2, mx2);
        float sc1 = __expf(m1 - mn1), sc2 = __expf(m2 - mn2);
        float ls1 = 0.f, ls2 = 0.f;
#pragma unroll
        for (int nj = 0; nj < 8; nj++) {
            s[nj][0] = __expf(s[nj][0] - mn1);
            s[nj][1] = __expf(s[nj][1] - mn1);
            s[nj][2] = __expf(s[nj][2] - mn2);
            s[nj][3] = __expf(s[nj][3] - mn2);
            ls1 += s[nj][0] + s[nj][1];
            ls2 += s[nj][2] + s[nj][3];
        }
        ls1 += __shfl_xor_sync(0xffffffffu, ls1, 1);
        ls1 += __shfl_xor_sync(0xffffffffu, ls1, 2);
        ls2 += __shfl_xor_sync(0xffffffffu, ls2, 1);
        ls2 += __shfl_xor_sync(0xffffffffu, ls2, 2);
        l1 = l1 * sc1 + ls1;  m1 = mn1;
        l2 = l2 * sc2 + ls2;  m2 = mn2;
#pragma unroll
        for (int nj = 0; nj < 8; nj++) {
            o[nj][0] *= sc1; o[nj][1] *= sc1;
            o[nj][2] *= sc2; o[nj][3] *= sc2;
        }

        // ---- PV (P split, V single, 2 MMAs) ----
#pragma unroll
        for (int kp = 0; kp < 4; kp++) {
            uint32_t pah[4], pal[4];
            {
                __half h0,h1,h2,h3,l0x,l1x,l2x,l3x;
                split1h(s[2*kp][0], h0, l0x); split1h(s[2*kp][1], h1, l1x);
                split1h(s[2*kp][2], h2, l2x); split1h(s[2*kp][3], h3, l3x);
                pah[0] = pack2hf(h0, h1); pah[1] = pack2hf(h2, h3);
                pal[0] = pack2hf(l0x, l1x); pal[1] = pack2hf(l2x, l3x);
                split1h(s[2*kp+1][0], h0, l0x); split1h(s[2*kp+1][1], h1, l1x);
                split1h(s[2*kp+1][2], h2, l2x); split1h(s[2*kp+1][3], h3, l3x);
                pah[2] = pack2hf(h0, h1); pah[3] = pack2hf(h2, h3);
                pal[2] = pack2hf(l0x, l1x); pal[3] = pack2hf(l2x, l3x);
            }
#pragma unroll
            for (int pd = 0; pd < 4; pd++) {
                uint32_t ro = (uint32_t)(kp * 16 + (lane & 15)) * AT_STR + pd * 32 + (lane >> 4) * 16;
                uint32_t qa[4];
                ldm4t(qa, bs + AMAT + ro);   // V (transposed)
                uint32_t b0[2] = {qa[0], qa[1]}, b1[2] = {qa[2], qa[3]};
                mma16816(o[2*pd],   pah, b0);
                mma16816(o[2*pd],   pal, b0);
                mma16816(o[2*pd+1], pah, b1);
                mma16816(o[2*pd+1], pal, b1);
            }
        }
        __syncthreads();
    }

    // ---- epilogue: 1/l, stage smem, coalesced write ----
    float i1 = 1.f / l1, i2 = 1.f / l2;
    float* Os = (float*)smc;     // [128][68]
    int r1 = w * 16 + (lane >> 2), r2 = r1 + 8;
#pragma unroll
    for (int nj = 0; nj < 8; nj++) {
        int c0 = nj * 8 + (lane & 3) * 2;
        Os[r1 * 68 + c0]     = o[nj][0] * i1;
        Os[r1 * 68 + c0 + 1] = o[nj][1] * i1;
        Os[r2 * 68 + c0]     = o[nj][2] * i2;
        Os[r2 * 68 + c0 + 1] = o[nj][3] * i2;
    }
    __syncthreads();
    int b = bh >> 4, h = bh & 15;
    for (int i = tid; i < 2048; i += 256) {
        int r = i >> 4, cq = (i & 15) * 4;
        float4 v = *(const float4*)&Os[r * 68 + cq];
        *(float4*)(g_attn + ((size_t)b * Tc + qbase + r) * Dc + h * HSc + cq) = v;
    }
}

// ---------------------------------------------------------------------------
extern "C" void kernel_launch(void* const* d_in, const int* in_sizes, int n_in,
                              void* d_out, int out_size)
{
    (void)in_sizes; (void)n_in; (void)out_size;
    const float* embds = (const float*)d_in[0];
    const float* Wq    = (const float*)d_in[1];
    const float* Wk    = (const float*)d_in[2];
    const float* Wv    = (const float*)d_in[3];
    const float* ln1_g = (const float*)d_in[4];
    const float* ln1_b = (const float*)d_in[5];
    const float* ln2_g = (const float*)d_in[6];
    const float* ln2_b = (const float*)d_in[7];
    const float* W1    = (const float*)d_in[8];
    const float* b1    = (const float*)d_in[9];
    const float* W2    = (const float*)d_in[10];
    const float* b2    = (const float*)d_in[11];
    float* out = (float*)d_out;

    cudaFuncSetAttribute(attn_mma_kernel, cudaFuncAttributeMaxDynamicSharedMemorySize,
                         ASM_TOTAL);
    cudaFuncSetAttribute(gemm_mma_kernel, cudaFuncAttributeMaxDynamicSharedMemorySize,
                         GSM_TOTAL);

    __half *x, *y, *wqh, *wql, *w1h, *w1l, *w2h, *w2l, *f1;
    cudaGetSymbolAddress((void**)&x, g_x);     cudaGetSymbolAddress((void**)&y, g_y);
    cudaGetSymbolAddress((void**)&wqh, g_wqkvh); cudaGetSymbolAddress((void**)&wql, g_wqkvl);
    cudaGetSymbolAddress((void**)&w1h, g_w1h); cudaGetSymbolAddress((void**)&w1l, g_w1l);
    cudaGetSymbolAddress((void**)&w2h, g_w2h); cudaGetSymbolAddress((void**)&w2l, g_w2l);
    cudaGetSymbolAddress((void**)&f1, g_ff1);

    ln1_kernel<<<NROW, 256>>>(embds, ln1_g, ln1_b);
    qkv_tsplit_kernel<<<dim3(2, 32, 48), dim3(32, 8)>>>(Wq, Wk, Wv);
    tsplit_kernel<<<dim3(128, 32), dim3(32, 8)>>>(W1, w1h, w1l, Dc, Fc);
    tsplit_kernel<<<dim3(32, 128), dim3(32, 8)>>>(W2, w2h, w2l, Fc, Dc);

    // QKV: A = x [4096,1024], B = wqkv split [3072,1024]
    gemm_mma_kernel<<<dim3(16, 24), 256, GSM_TOTAL>>>(x, wqh, wql,
                                                      Dc, 0, nullptr, nullptr);
    attn_mma_kernel<<<dim3(Tc / 128, Bc * Hc), 256, ASM_TOTAL>>>();
    add_ln_kernel<<<NROW, 256>>>(embds, ln2_g, ln2_b);
    // FFN1: A = y [4096,1024], B = w1t split [4096,1024]
    gemm_mma_kernel<<<dim3(16, 32), 256, GSM_TOTAL>>>(y, w1h, w1l,
                                                      Dc, 1, b1, nullptr);
    // FFN2: A = ff1 [4096,4096], B = w2t split [1024,4096]
    gemm_mma_kernel<<<dim3(16, 8), 256, GSM_TOTAL>>>(f1, w2h, w2l,
                                                     Fc, 2, b2, out);
}